// round 6
// baseline (speedup 1.0000x reference)
#include <cuda_runtime.h>

#define EPSV 1e-7f
#define NPTS 131072
#define NT3  393216        // NPTS*3
#define NSEG 32

// ---- transposed-weight offsets (in floats) within d_wt ----
#define O_W1F 0
#define O_W1D 16384
#define O_W2F 32768
#define O_W2D 49152
#define O_W3  65536
#define O_WD1 81920
#define O_WR3 98304
#define O_W4F 114688
#define O_W4D 180224
#define O_W5  245760
#define O_WD2 311296
#define O_WR5 376832
#define WT_TOTAL 442368

// ---- static device scratch (no allocations allowed) ----
__device__ float d_wt[WT_TOTAL];
__device__ float d_g3s[128ull * (unsigned long long)NT3];   // vn3 output, layout [c][n*3+j]
__device__ float d_h5s[256ull * (unsigned long long)NT3];   // vn5 output, layout [c][n*3+j]
__device__ float d_r3[NSEG * 128 * 3];                      // relu3 output per segment
__device__ unsigned long long d_key1[NSEG * 128];
__device__ unsigned long long d_key2[NSEG * 256];

typedef unsigned long long u64;

// ---------------------------------------------------------------------------
// helpers
// ---------------------------------------------------------------------------
__device__ __forceinline__ u64 packkey(float dot, unsigned int n) {
    unsigned int u = __float_as_uint(dot);
    u = (u & 0x80000000u) ? ~u : (u | 0x80000000u);   // order-preserving float->uint
    return ((u64)u << 32) | (u64)(0xFFFFFFFFu - n);   // tie -> min n
}

__device__ __forceinline__ u64 shfl_xor_u64(u64 v, int m) {
    unsigned int lo = (unsigned int)v;
    unsigned int hi = (unsigned int)(v >> 32);
    lo = __shfl_xor_sync(0xFFFFFFFFu, lo, m);
    hi = __shfl_xor_sync(0xFFFFFFFFu, hi, m);
    return ((u64)hi << 32) | lo;
}

// packed fp32x2 FMA: d = a * b + d (lanewise, exact fp32 per lane)
__device__ __forceinline__ void ffma2(u64& d, u64 a, u64 b) {
    asm("fma.rn.f32x2 %0, %1, %2, %0;" : "+l"(d) : "l"(a), "l"(b));
}
__device__ __forceinline__ u64 packdup(float x) {
    u64 r;
    asm("mov.b64 %0, {%1, %1};" : "=l"(r) : "r"(__float_as_uint(x)));
    return r;
}
__device__ __forceinline__ void unpack2(u64 v, float& lo, float& hi) {
    unsigned int l, h;
    asm("mov.b64 {%0, %1}, %2;" : "=r"(l), "=r"(h) : "l"(v));
    lo = __uint_as_float(l);
    hi = __uint_as_float(h);
}

// cp.async 16B helpers
__device__ __forceinline__ void cpa16(float* smdst, const float4* gsrc) {
    unsigned s = (unsigned)__cvta_generic_to_shared(smdst);
    asm volatile("cp.async.cg.shared.global [%0], [%1], 16;" :: "r"(s), "l"(gsrc));
}
__device__ __forceinline__ void cp_commit() { asm volatile("cp.async.commit_group;"); }
__device__ __forceinline__ void cp_wait1() { asm volatile("cp.async.wait_group 1;" ::: "memory"); }
__device__ __forceinline__ void cp_wait0() { asm volatile("cp.async.wait_group 0;" ::: "memory"); }

// ---------------------------------------------------------------------------
// matmul cores. Thread tile 8 channels (4 packed pairs) x 6 cols (2 points).
// Activations bufIn are stored DUPLICATED: u64 element = {v,v}, so b-operands
// load pre-packed (3 x LDS.128 per kk, no MOV packs).
// wT k-major: wT[k*OTOT + o]. smW: double-buffered cp.async weight staging.
// COLS is in u64 units.
// ---------------------------------------------------------------------------
template<int K, int OTOT, int COLS, int KT>
__device__ __forceinline__ void mm_pair2(const float* __restrict__ wfT, const float* __restrict__ wdT,
                                         const u64* __restrict__ bufIn, float* smW,
                                         u64 accP[4][6], u64 accD[4][6],
                                         int o_base, int col_base, int tid)
{
    constexpr int TW    = KT * OTOT;
    constexpr int BUFSZ = 2 * TW;
    constexpr int NT    = K / KT;
    constexpr int PER   = TW / 4 / 256;

    {
        float* df = smW;
        float* dd = smW + TW;
        const float4* sf = (const float4*)(wfT);
        const float4* sd = (const float4*)(wdT);
#pragma unroll
        for (int r = 0; r < PER; r++) {
            cpa16(df + (tid + 256 * r) * 4, sf + tid + 256 * r);
            cpa16(dd + (tid + 256 * r) * 4, sd + tid + 256 * r);
        }
        cp_commit();
    }
    for (int t = 0; t < NT; t++) {
        if (t + 1 < NT) {
            float* df = smW + ((t + 1) & 1) * BUFSZ;
            float* dd = df + TW;
            const float4* sf = (const float4*)(wfT + (t + 1) * KT * OTOT);
            const float4* sd = (const float4*)(wdT + (t + 1) * KT * OTOT);
#pragma unroll
            for (int r = 0; r < PER; r++) {
                cpa16(df + (tid + 256 * r) * 4, sf + tid + 256 * r);
                cpa16(dd + (tid + 256 * r) * 4, sd + tid + 256 * r);
            }
            cp_commit();
            cp_wait1();
        } else {
            cp_wait0();
        }
        __syncthreads();
        const float* Wf = smW + (t & 1) * BUFSZ;
        const float* Wd = Wf + TW;
#pragma unroll
        for (int kk = 0; kk < KT; kk++) {
            const ulonglong2* ar = (const ulonglong2*)(Wf + kk * OTOT + o_base);
            const ulonglong2* dr = (const ulonglong2*)(Wd + kk * OTOT + o_base);
            const ulonglong2* br = (const ulonglong2*)(bufIn + (size_t)(t * KT + kk) * COLS + col_base);
            ulonglong2 q0 = br[0], q1 = br[1], q2 = br[2];
            u64 b2[6] = {q0.x, q0.y, q1.x, q1.y, q2.x, q2.y};
            ulonglong2 af0 = ar[0], af1 = ar[1], ad0 = dr[0], ad1 = dr[1];
            u64 a2f[4] = {af0.x, af0.y, af1.x, af1.y};
            u64 a2d[4] = {ad0.x, ad0.y, ad1.x, ad1.y};
#pragma unroll
            for (int op = 0; op < 4; op++)
#pragma unroll
                for (int cc = 0; cc < 6; cc++) {
                    ffma2(accP[op][cc], a2f[op], b2[cc]);
                    ffma2(accD[op][cc], a2d[op], b2[cc]);
                }
        }
        __syncthreads();
    }
}

template<int K, int OTOT, int COLS, int KT>
__device__ __forceinline__ void mm_one2(const float* __restrict__ wT,
                                        const u64* __restrict__ bufIn, float* smW,
                                        u64 acc[4][6], int o_base, int col_base, int tid)
{
    constexpr int TW  = KT * OTOT;
    constexpr int NT  = K / KT;
    constexpr int PER = TW / 4 / 256;

    {
        const float4* sf = (const float4*)(wT);
#pragma unroll
        for (int r = 0; r < PER; r++)
            cpa16(smW + (tid + 256 * r) * 4, sf + tid + 256 * r);
        cp_commit();
    }
    for (int t = 0; t < NT; t++) {
        if (t + 1 < NT) {
            float* df = smW + ((t + 1) & 1) * TW;
            const float4* sf = (const float4*)(wT + (t + 1) * KT * OTOT);
#pragma unroll
            for (int r = 0; r < PER; r++)
                cpa16(df + (tid + 256 * r) * 4, sf + tid + 256 * r);
            cp_commit();
            cp_wait1();
        } else {
            cp_wait0();
        }
        __syncthreads();
        const float* Wf = smW + (t & 1) * TW;
#pragma unroll
        for (int kk = 0; kk < KT; kk++) {
            const ulonglong2* ar = (const ulonglong2*)(Wf + kk * OTOT + o_base);
            const ulonglong2* br = (const ulonglong2*)(bufIn + (size_t)(t * KT + kk) * COLS + col_base);
            ulonglong2 q0 = br[0], q1 = br[1], q2 = br[2];
            u64 b2[6] = {q0.x, q0.y, q1.x, q1.y, q2.x, q2.y};
            ulonglong2 af0 = ar[0], af1 = ar[1];
            u64 a2[4] = {af0.x, af0.y, af1.x, af1.y};
#pragma unroll
            for (int op = 0; op < 4; op++)
#pragma unroll
                for (int cc = 0; cc < 6; cc++)
                    ffma2(acc[op][cc], a2[op], b2[cc]);
        }
        __syncthreads();
    }
}

__device__ __forceinline__ void zero_acc(u64 a[4][6]) {
#pragma unroll
    for (int op = 0; op < 4; op++)
#pragma unroll
        for (int cc = 0; cc < 6; cc++) a[op][cc] = 0ull;
}

__device__ __forceinline__ void unpack_acc(const u64 a[4][6], float f[8][6]) {
#pragma unroll
    for (int op = 0; op < 4; op++)
#pragma unroll
        for (int cc = 0; cc < 6; cc++)
            unpack2(a[op][cc], f[2 * op][cc], f[2 * op + 1][cc]);
}

// VN LeakyReLU (ns=0): keep p where dot>=0 else p - dot/(dn+eps)*d. 8 ch x 2 points.
__device__ __forceinline__ void vn_combine(float accP[8][6], float accD[8][6])
{
#pragma unroll
    for (int oo = 0; oo < 8; oo++)
#pragma unroll
        for (int p = 0; p < 2; p++) {
            float p0 = accP[oo][3 * p], p1 = accP[oo][3 * p + 1], p2 = accP[oo][3 * p + 2];
            float q0 = accD[oo][3 * p], q1 = accD[oo][3 * p + 1], q2 = accD[oo][3 * p + 2];
            float dot = p0 * q0 + p1 * q1 + p2 * q2;
            float dn  = q0 * q0 + q1 * q1 + q2 * q2;
            if (dot < 0.f) {
                float s = dot / (dn + EPSV);
                accP[oo][3 * p]     = p0 - s * q0;
                accP[oo][3 * p + 1] = p1 - s * q1;
                accP[oo][3 * p + 2] = p2 - s * q2;
            }
        }
}

// store duplicated u64 elements into bufIn (COLS in u64 units)
template<int COLS>
__device__ __forceinline__ void store_tile_dup(u64* buf, float f[8][6], int o_base, int col_base)
{
#pragma unroll
    for (int oo = 0; oo < 8; oo++) {
        u64* r = buf + (size_t)(o_base + oo) * COLS + col_base;
#pragma unroll
        for (int cc = 0; cc < 6; cc++) r[cc] = packdup(f[oo][cc]);
    }
}

// ---------------------------------------------------------------------------
// setup kernels
// ---------------------------------------------------------------------------
__global__ void k_initkeys()
{
    int i = blockIdx.x * blockDim.x + threadIdx.x;
    if (i < NSEG * 128) d_key1[i] = 0ull;
    if (i < NSEG * 256) d_key2[i] = 0ull;
}

struct TList {
    const float* src[7];
    int off[7];
};

// W[o][c] (OxC) -> d_wt[off + c*O + o]; one matrix per blockIdx.z
__global__ void k_tmany(TList tl, int O, int C)
{
    __shared__ float t[32][33];
    const float* src = tl.src[blockIdx.z];
    int dstOff = tl.off[blockIdx.z];
    int cb = blockIdx.x * 32, ob = blockIdx.y * 32;
    int x = threadIdx.x, y = threadIdx.y;
    for (int i = y; i < 32; i += 8) t[i][x] = src[(size_t)(ob + i) * C + cb + x];
    __syncthreads();
    for (int i = y; i < 32; i += 8) d_wt[dstOff + (size_t)(cb + i) * O + ob + x] = t[x][i];
}

// ---------------------------------------------------------------------------
// stage 1: vn1 -> vn2 -> vn3 -> (store g3, argmax over Wd1 dot)
// 32 points per CTA, 256 threads (16x16 map), KT=32
// smem: bufA u64[128][96] (96KB) + smW 4*32*128 floats (64KB) = 160KB
// ---------------------------------------------------------------------------
__global__ void __launch_bounds__(256, 1) k_stage1(const float* __restrict__ x,
                                                   const int* __restrict__ radius)
{
    extern __shared__ u64 smu[];
    u64*   bufA = smu;                       // [128][96] duplicated
    float* smW  = (float*)(smu + 12288);     // 4 x [32][128]
    int tid = threadIdx.x;
    int n0 = blockIdx.x * 32;

    // load X tile transposed+dup: bufA[c][p*3+j] = {x,x}
    const float* xg = x + (size_t)n0 * 384;
    for (int i4 = tid; i4 < 3072; i4 += 256) {
        float4 v = ((const float4*)xg)[i4];
        int lin = i4 * 4;
        int p = lin / 384, r = lin % 384;
        float vv[4] = {v.x, v.y, v.z, v.w};
#pragma unroll
        for (int e = 0; e < 4; e++) {
            int rr = r + e;
            int c = rr / 3, j = rr - c * 3;
            bufA[(size_t)c * 96 + p * 3 + j] = packdup(vv[e]);
        }
    }

    int ty = tid >> 4, tx = tid & 15;
    int o_base = ty * 8, col_base = tx * 6;   // col_base in u64 units

    u64 aP[4][6], aD[4][6];
    float fP[8][6], fD[8][6];

    // L1: vn1  (mm ends with a barrier -> safe to overwrite bufA)
    zero_acc(aP); zero_acc(aD);
    mm_pair2<128, 128, 96, 32>(d_wt + O_W1F, d_wt + O_W1D, bufA, smW, aP, aD, o_base, col_base, tid);
    unpack_acc(aP, fP); unpack_acc(aD, fD);
    vn_combine(fP, fD);
    store_tile_dup<96>(bufA, fP, o_base, col_base);

    // L2: vn2
    zero_acc(aP); zero_acc(aD);
    mm_pair2<128, 128, 96, 32>(d_wt + O_W2F, d_wt + O_W2D, bufA, smW, aP, aD, o_base, col_base, tid);
    unpack_acc(aP, fP); unpack_acc(aD, fD);
    vn_combine(fP, fD);
    store_tile_dup<96>(bufA, fP, o_base, col_base);

    // L3: vn3
    zero_acc(aP);
    mm_one2<128, 128, 96, 32>(d_wt + O_W3, bufA, smW, aP, o_base, col_base, tid);
    unpack_acc(aP, fP);
    store_tile_dup<96>(bufA, fP, o_base, col_base);

    // write g3 to global scratch (layout [c][n*3+j])
#pragma unroll
    for (int oo = 0; oo < 8; oo++) {
        float* g = d_g3s + (size_t)(o_base + oo) * NT3 + (size_t)n0 * 3 + col_base;
#pragma unroll
        for (int cc = 0; cc < 6; cc++) g[cc] = fP[oo][cc];
    }

    // L3d: d = Wd1 * Y   (bufA holds Y)
    zero_acc(aD);
    mm_one2<128, 128, 96, 32>(d_wt + O_WD1, bufA, smW, aD, o_base, col_base, tid);
    unpack_acc(aD, fD);

    // per-(channel,point) dot, argmax reduce across the CTA's 32 points
    int seg = radius[n0];
    unsigned int nA = (unsigned int)(n0 + 2 * tx);
#pragma unroll
    for (int oo = 0; oo < 8; oo++) {
        float dot0 = fP[oo][0] * fD[oo][0] + fP[oo][1] * fD[oo][1] + fP[oo][2] * fD[oo][2];
        float dot1 = fP[oo][3] * fD[oo][3] + fP[oo][4] * fD[oo][4] + fP[oo][5] * fD[oo][5];
        u64 b0 = packkey(dot0, nA);
        u64 b1 = packkey(dot1, nA + 1);
        u64 best = (b0 > b1) ? b0 : b1;
#pragma unroll
        for (int m = 1; m < 16; m <<= 1) {
            u64 o = shfl_xor_u64(best, m);
            if (o > best) best = o;
        }
        if (tx == 0) atomicMax(&d_key1[seg * 128 + o_base + oo], best);
    }
}

// ---------------------------------------------------------------------------
// gather + relu3  (one block per segment, 128 threads)
// ---------------------------------------------------------------------------
__global__ void k_relu3()
{
    __shared__ float G[128][3];
    int seg = blockIdx.x, c = threadIdx.x;
    u64 key = d_key1[seg * 128 + c];
    unsigned int idx = 0xFFFFFFFFu - (unsigned int)(key & 0xFFFFFFFFull);
    if (idx >= NPTS) idx = 0;
    float g0 = d_g3s[(size_t)c * NT3 + (size_t)idx * 3 + 0];
    float g1 = d_g3s[(size_t)c * NT3 + (size_t)idx * 3 + 1];
    float g2 = d_g3s[(size_t)c * NT3 + (size_t)idx * 3 + 2];
    G[c][0] = g0; G[c][1] = g1; G[c][2] = g2;
    __syncthreads();
    float a0 = 0.f, a1 = 0.f, a2 = 0.f;
    const float* w = d_wt + O_WR3;   // k-major: w[k*128 + c]
    for (int k = 0; k < 128; k++) {
        float ww = w[k * 128 + c];
        a0 += ww * G[k][0]; a1 += ww * G[k][1]; a2 += ww * G[k][2];
    }
    float dot = g0 * a0 + g1 * a1 + g2 * a2;
    float dn  = a0 * a0 + a1 * a1 + a2 * a2;
    float o0 = g0, o1 = g1, o2 = g2;
    if (dot < 0.f) {
        float s = dot / (dn + EPSV);
        o0 -= s * a0; o1 -= s * a1; o2 -= s * a2;
    }
    d_r3[seg * 384 + c * 3 + 0] = o0;
    d_r3[seg * 384 + c * 3 + 1] = o1;
    d_r3[seg * 384 + c * 3 + 2] = o2;
}

// ---------------------------------------------------------------------------
// stage 2: concat -> vn4 -> vn5 -> (store h5, argmax over Wd2 dot)
// 16 points per CTA, 256 threads (32x8 map), KT=32
// smem: bufA u64[256][48] (96KB) + smW 4*32*256 floats (128KB) = 224KB
// ---------------------------------------------------------------------------
__global__ void __launch_bounds__(256, 1) k_stage2(const float* __restrict__ x,
                                                   const int* __restrict__ radius)
{
    extern __shared__ u64 smu[];
    u64*   bufA = smu;                       // [256][48] duplicated
    float* smW  = (float*)(smu + 12288);     // 4 x [32][256]
    int tid = threadIdx.x;
    int n0 = blockIdx.x * 16;
    int seg = radius[n0];

    // x part: bufA[c][p*3+j] = {x,x}, c < 128
    const float* xg = x + (size_t)n0 * 384;
    for (int i4 = tid; i4 < 1536; i4 += 256) {
        float4 v = ((const float4*)xg)[i4];
        int lin = i4 * 4;
        int p = lin / 384, r = lin % 384;
        float vv[4] = {v.x, v.y, v.z, v.w};
#pragma unroll
        for (int e = 0; e < 4; e++) {
            int rr = r + e;
            int c = rr / 3, j = rr - c * 3;
            bufA[(size_t)c * 48 + p * 3 + j] = packdup(vv[e]);
        }
    }
    // r3 broadcast part: bufA[128+c][p*3+j] = {r3,r3}
    const float* r3s = d_r3 + seg * 384;
    for (int i = tid; i < 128 * 48; i += 256) {
        int c = i / 48, col = i - c * 48;
        int j = col % 3;
        bufA[(size_t)(128 + c) * 48 + col] = packdup(r3s[c * 3 + j]);
    }

    int ty = tid >> 3, tx = tid & 7;
    int o_base = ty * 8, col_base = tx * 6;   // col_base in u64 units

    u64 aP[4][6], aD[4][6];
    float fP[8][6], fD[8][6];

    // L4: vn4
    zero_acc(aP); zero_acc(aD);
    mm_pair2<256, 256, 48, 32>(d_wt + O_W4F, d_wt + O_W4D, bufA, smW, aP, aD, o_base, col_base, tid);
    unpack_acc(aP, fP); unpack_acc(aD, fD);
    vn_combine(fP, fD);
    store_tile_dup<48>(bufA, fP, o_base, col_base);

    // L5: vn5
    zero_acc(aP);
    mm_one2<256, 256, 48, 32>(d_wt + O_W5, bufA, smW, aP, o_base, col_base, tid);
    unpack_acc(aP, fP);
    store_tile_dup<48>(bufA, fP, o_base, col_base);

    // write h5 scratch (layout [c][n*3+j])
#pragma unroll
    for (int oo = 0; oo < 8; oo++) {
        float* g = d_h5s + (size_t)(o_base + oo) * NT3 + (size_t)n0 * 3 + col_base;
#pragma unroll
        for (int cc = 0; cc < 6; cc++) g[cc] = fP[oo][cc];
    }

    // L5d: d = Wd2 * Y   (bufA holds Y)
    zero_acc(aD);
    mm_one2<256, 256, 48, 32>(d_wt + O_WD2, bufA, smW, aD, o_base, col_base, tid);
    unpack_acc(aD, fD);

    unsigned int nA = (unsigned int)(n0 + 2 * tx);
#pragma unroll
    for (int oo = 0; oo < 8; oo++) {
        float dot0 = fP[oo][0] * fD[oo][0] + fP[oo][1] * fD[oo][1] + fP[oo][2] * fD[oo][2];
        float dot1 = fP[oo][3] * fD[oo][3] + fP[oo][4] * fD[oo][4] + fP[oo][5] * fD[oo][5];
        u64 b0 = packkey(dot0, nA);
        u64 b1 = packkey(dot1, nA + 1);
        u64 best = (b0 > b1) ? b0 : b1;
#pragma unroll
        for (int m = 1; m < 8; m <<= 1) {
            u64 o = shfl_xor_u64(best, m);
            if (o > best) best = o;
        }
        if (tx == 0) atomicMax(&d_key2[seg * 256 + o_base + oo], best);
    }
}

// ---------------------------------------------------------------------------
// gather + relu5 -> output  (one block per segment, 256 threads)
// ---------------------------------------------------------------------------
__global__ void k_relu5(float* __restrict__ out)
{
    __shared__ float G[256][3];
    int seg = blockIdx.x, c = threadIdx.x;
    u64 key = d_key2[seg * 256 + c];
    unsigned int idx = 0xFFFFFFFFu - (unsigned int)(key & 0xFFFFFFFFull);
    if (idx >= NPTS) idx = 0;
    float g0 = d_h5s[(size_t)c * NT3 + (size_t)idx * 3 + 0];
    float g1 = d_h5s[(size_t)c * NT3 + (size_t)idx * 3 + 1];
    float g2 = d_h5s[(size_t)c * NT3 + (size_t)idx * 3 + 2];
    G[c][0] = g0; G[c][1] = g1; G[c][2] = g2;
    __syncthreads();
    float a0 = 0.f, a1 = 0.f, a2 = 0.f;
    const float* w = d_wt + O_WR5;   // k-major: w[k*256 + c]
    for (int k = 0; k < 256; k++) {
        float ww = w[k * 256 + c];
        a0 += ww * G[k][0]; a1 += ww * G[k][1]; a2 += ww * G[k][2];
    }
    float dot = g0 * a0 + g1 * a1 + g2 * a2;
    float dn  = a0 * a0 + a1 * a1 + a2 * a2;
    float o0 = g0, o1 = g1, o2 = g2;
    if (dot < 0.f) {
        float s = dot / (dn + EPSV);
        o0 -= s * a0; o1 -= s * a1; o2 -= s * a2;
    }
    out[seg * 768 + c * 3 + 0] = o0;
    out[seg * 768 + c * 3 + 1] = o1;
    out[seg * 768 + c * 3 + 2] = o2;
}

// ---------------------------------------------------------------------------
// host launcher
// ---------------------------------------------------------------------------
extern "C" void kernel_launch(void* const* d_in, const int* in_sizes, int n_in,
                              void* d_out, int out_size)
{
    const float* x      = (const float*)d_in[0];
    const int*   radius = (const int*)d_in[1];

    cudaFuncSetAttribute(k_stage1, cudaFuncAttributeMaxDynamicSharedMemorySize, 163840);
    cudaFuncSetAttribute(k_stage2, cudaFuncAttributeMaxDynamicSharedMemorySize, 229376);

    k_initkeys<<<32, 256>>>();

    dim3 tb(32, 8);
    TList t128;
    t128.src[0] = (const float*)d_in[2];  t128.off[0] = O_W1F;
    t128.src[1] = (const float*)d_in[3];  t128.off[1] = O_W1D;
    t128.src[2] = (const float*)d_in[4];  t128.off[2] = O_W2F;
    t128.src[3] = (const float*)d_in[5];  t128.off[3] = O_W2D;
    t128.src[4] = (const float*)d_in[6];  t128.off[4] = O_W3;
    t128.src[5] = (const float*)d_in[7];  t128.off[5] = O_WD1;
    t128.src[6] = (const float*)d_in[8];  t128.off[6] = O_WR3;
    k_tmany<<<dim3(4, 4, 7), tb>>>(t128, 128, 128);

    TList t256;
    t256.src[0] = (const float*)d_in[9];   t256.off[0] = O_W4F;
    t256.src[1] = (const float*)d_in[10];  t256.off[1] = O_W4D;
    t256.src[2] = (const float*)d_in[11];  t256.off[2] = O_W5;
    t256.src[3] = (const float*)d_in[12];  t256.off[3] = O_WD2;
    t256.src[4] = (const float*)d_in[13];  t256.off[4] = O_WR5;
    t256.src[5] = t256.src[4];             t256.off[5] = O_WR5;  // unused (grid.z=5)
    t256.src[6] = t256.src[4];             t256.off[6] = O_WR5;
    k_tmany<<<dim3(8, 8, 5), tb>>>(t256, 256, 256);

    k_stage1<<<NPTS / 32, 256, 163840>>>(x, radius);
    k_relu3<<<NSEG, 128>>>();
    k_stage2<<<NPTS / 16, 256, 229376>>>(x, radius);
    k_relu5<<<NSEG, 256>>>((float*)d_out);
}

// round 7
// speedup vs baseline: 1.1020x; 1.1020x over previous
#include <cuda_runtime.h>

#define EPSV 1e-7f
#define NPTS 131072
#define NT3  393216        // NPTS*3
#define NSEG 32

// ---- transposed-weight offsets (in floats) within d_wt ----
#define O_W1F 0
#define O_W1D 16384
#define O_W2F 32768
#define O_W2D 49152
#define O_W3  65536
#define O_WD1 81920
#define O_WR3 98304
#define O_W4F 114688
#define O_W4D 180224
#define O_W5  245760
#define O_WD2 311296
#define O_WR5 376832
#define WT_TOTAL 442368

// ---- static device scratch (no allocations allowed) ----
__device__ float d_wt[WT_TOTAL];
__device__ float d_g3s[128ull * (unsigned long long)NT3];   // vn3 output, layout [c][n*3+j]
__device__ float d_h5s[256ull * (unsigned long long)NT3];   // vn5 output, layout [c][n*3+j]
__device__ float d_r3[NSEG * 128 * 3];                      // relu3 output per segment
__device__ unsigned long long d_key1[NSEG * 128];
__device__ unsigned long long d_key2[NSEG * 256];

typedef unsigned long long u64;

// ---------------------------------------------------------------------------
// helpers
// ---------------------------------------------------------------------------
__device__ __forceinline__ u64 packkey(float dot, unsigned int n) {
    unsigned int u = __float_as_uint(dot);
    u = (u & 0x80000000u) ? ~u : (u | 0x80000000u);   // order-preserving float->uint
    return ((u64)u << 32) | (u64)(0xFFFFFFFFu - n);   // tie -> min n
}

__device__ __forceinline__ u64 shfl_xor_u64(u64 v, int m) {
    unsigned int lo = (unsigned int)v;
    unsigned int hi = (unsigned int)(v >> 32);
    lo = __shfl_xor_sync(0xFFFFFFFFu, lo, m);
    hi = __shfl_xor_sync(0xFFFFFFFFu, hi, m);
    return ((u64)hi << 32) | lo;
}

// packed fp32x2 FMA: d = a * b + d (lanewise, exact fp32 per lane)
__device__ __forceinline__ void ffma2(u64& d, u64 a, u64 b) {
    asm("fma.rn.f32x2 %0, %1, %2, %0;" : "+l"(d) : "l"(a), "l"(b));
}
__device__ __forceinline__ u64 packdup(float x) {
    u64 r;
    asm("mov.b64 %0, {%1, %1};" : "=l"(r) : "r"(__float_as_uint(x)));
    return r;
}
__device__ __forceinline__ void unpack2(u64 v, float& lo, float& hi) {
    unsigned int l, h;
    asm("mov.b64 {%0, %1}, %2;" : "=r"(l), "=r"(h) : "l"(v));
    lo = __uint_as_float(l);
    hi = __uint_as_float(h);
}

// cp.async 16B helpers
__device__ __forceinline__ void cpa16(float* smdst, const float4* gsrc) {
    unsigned s = (unsigned)__cvta_generic_to_shared(smdst);
    asm volatile("cp.async.cg.shared.global [%0], [%1], 16;" :: "r"(s), "l"(gsrc));
}
__device__ __forceinline__ void cp_commit() { asm volatile("cp.async.commit_group;"); }
__device__ __forceinline__ void cp_wait0() { asm volatile("cp.async.wait_group 0;" ::: "memory"); }

// ---------------------------------------------------------------------------
// matmul cores. Thread tile 8 channels (4 packed pairs) x 6 cols (2 points).
// wT k-major: wT[k*OTOT + o]. smW: double-buffered cp.async weight staging.
// Pipeline per tile t: wait(t's data) -> BAR -> issue cp(t+1) -> compute(t).
// Single barrier per tile is safe: any warp past BAR(t) implies all warps
// finished compute(t-1), so slot (t+1)&1 has no remaining readers.
// Trailing BAR protects caller's bufIn overwrite.
// ---------------------------------------------------------------------------
template<int K, int OTOT, int COLS, int KT>
__device__ __forceinline__ void mm_pair2(const float* __restrict__ wfT, const float* __restrict__ wdT,
                                         const float* __restrict__ bufIn, float* smW,
                                         u64 accP[4][6], u64 accD[4][6],
                                         int o_base, int col_base, int tid)
{
    constexpr int TW    = KT * OTOT;
    constexpr int BUFSZ = 2 * TW;
    constexpr int NT    = K / KT;
    constexpr int PER   = TW / 4 / 256;

    {
        const float4* sf = (const float4*)(wfT);
        const float4* sd = (const float4*)(wdT);
#pragma unroll
        for (int r = 0; r < PER; r++) {
            cpa16(smW +      (tid + 256 * r) * 4, sf + tid + 256 * r);
            cpa16(smW + TW + (tid + 256 * r) * 4, sd + tid + 256 * r);
        }
        cp_commit();
    }
    for (int t = 0; t < NT; t++) {
        cp_wait0();
        __syncthreads();
        if (t + 1 < NT) {
            float* df = smW + ((t + 1) & 1) * BUFSZ;
            float* dd = df + TW;
            const float4* sf = (const float4*)(wfT + (t + 1) * KT * OTOT);
            const float4* sd = (const float4*)(wdT + (t + 1) * KT * OTOT);
#pragma unroll
            for (int r = 0; r < PER; r++) {
                cpa16(df + (tid + 256 * r) * 4, sf + tid + 256 * r);
                cpa16(dd + (tid + 256 * r) * 4, sd + tid + 256 * r);
            }
            cp_commit();
        }
        const float* Wf = smW + (t & 1) * BUFSZ;
        const float* Wd = Wf + TW;
#pragma unroll
        for (int kk = 0; kk < KT; kk++) {
            const ulonglong2* ar = (const ulonglong2*)(Wf + kk * OTOT + o_base);
            const ulonglong2* dr = (const ulonglong2*)(Wd + kk * OTOT + o_base);
            const float* br = bufIn + (t * KT + kk) * COLS + col_base;
            float2 b01 = *(const float2*)(br);
            float2 b23 = *(const float2*)(br + 2);
            float2 b45 = *(const float2*)(br + 4);
            u64 b2[6];
            b2[0] = packdup(b01.x); b2[1] = packdup(b01.y);
            b2[2] = packdup(b23.x); b2[3] = packdup(b23.y);
            b2[4] = packdup(b45.x); b2[5] = packdup(b45.y);
            ulonglong2 af0 = ar[0], af1 = ar[1], ad0 = dr[0], ad1 = dr[1];
            u64 a2f[4] = {af0.x, af0.y, af1.x, af1.y};
            u64 a2d[4] = {ad0.x, ad0.y, ad1.x, ad1.y};
#pragma unroll
            for (int op = 0; op < 4; op++)
#pragma unroll
                for (int cc = 0; cc < 6; cc++) {
                    ffma2(accP[op][cc], a2f[op], b2[cc]);
                    ffma2(accD[op][cc], a2d[op], b2[cc]);
                }
        }
    }
    __syncthreads();
}

template<int K, int OTOT, int COLS, int KT>
__device__ __forceinline__ void mm_one2(const float* __restrict__ wT,
                                        const float* __restrict__ bufIn, float* smW,
                                        u64 acc[4][6], int o_base, int col_base, int tid)
{
    constexpr int TW  = KT * OTOT;
    constexpr int NT  = K / KT;
    constexpr int PER = TW / 4 / 256;

    {
        const float4* sf = (const float4*)(wT);
#pragma unroll
        for (int r = 0; r < PER; r++)
            cpa16(smW + (tid + 256 * r) * 4, sf + tid + 256 * r);
        cp_commit();
    }
    for (int t = 0; t < NT; t++) {
        cp_wait0();
        __syncthreads();
        if (t + 1 < NT) {
            float* df = smW + ((t + 1) & 1) * TW;
            const float4* sf = (const float4*)(wT + (t + 1) * KT * OTOT);
#pragma unroll
            for (int r = 0; r < PER; r++)
                cpa16(df + (tid + 256 * r) * 4, sf + tid + 256 * r);
            cp_commit();
        }
        const float* Wf = smW + (t & 1) * TW;
#pragma unroll
        for (int kk = 0; kk < KT; kk++) {
            const ulonglong2* ar = (const ulonglong2*)(Wf + kk * OTOT + o_base);
            const float* br = bufIn + (t * KT + kk) * COLS + col_base;
            float2 b01 = *(const float2*)(br);
            float2 b23 = *(const float2*)(br + 2);
            float2 b45 = *(const float2*)(br + 4);
            u64 b2[6];
            b2[0] = packdup(b01.x); b2[1] = packdup(b01.y);
            b2[2] = packdup(b23.x); b2[3] = packdup(b23.y);
            b2[4] = packdup(b45.x); b2[5] = packdup(b45.y);
            ulonglong2 af0 = ar[0], af1 = ar[1];
            u64 a2[4] = {af0.x, af0.y, af1.x, af1.y};
#pragma unroll
            for (int op = 0; op < 4; op++)
#pragma unroll
                for (int cc = 0; cc < 6; cc++)
                    ffma2(acc[op][cc], a2[op], b2[cc]);
        }
    }
    __syncthreads();
}

__device__ __forceinline__ void zero_acc(u64 a[4][6]) {
#pragma unroll
    for (int op = 0; op < 4; op++)
#pragma unroll
        for (int cc = 0; cc < 6; cc++) a[op][cc] = 0ull;
}

__device__ __forceinline__ void unpack_acc(const u64 a[4][6], float f[8][6]) {
#pragma unroll
    for (int op = 0; op < 4; op++)
#pragma unroll
        for (int cc = 0; cc < 6; cc++)
            unpack2(a[op][cc], f[2 * op][cc], f[2 * op + 1][cc]);
}

// VN LeakyReLU (ns=0): keep p where dot>=0 else p - dot/(dn+eps)*d. 8 ch x 2 points.
__device__ __forceinline__ void vn_combine(float accP[8][6], float accD[8][6])
{
#pragma unroll
    for (int oo = 0; oo < 8; oo++)
#pragma unroll
        for (int p = 0; p < 2; p++) {
            float p0 = accP[oo][3 * p], p1 = accP[oo][3 * p + 1], p2 = accP[oo][3 * p + 2];
            float q0 = accD[oo][3 * p], q1 = accD[oo][3 * p + 1], q2 = accD[oo][3 * p + 2];
            float dot = p0 * q0 + p1 * q1 + p2 * q2;
            float dn  = q0 * q0 + q1 * q1 + q2 * q2;
            if (dot < 0.f) {
                float s = dot / (dn + EPSV);
                accP[oo][3 * p]     = p0 - s * q0;
                accP[oo][3 * p + 1] = p1 - s * q1;
                accP[oo][3 * p + 2] = p2 - s * q2;
            }
        }
}

template<int COLS>
__device__ __forceinline__ void store_tile(float* buf, float acc[8][6], int o_base, int col_base)
{
#pragma unroll
    for (int oo = 0; oo < 8; oo++) {
        float* r = buf + (o_base + oo) * COLS + col_base;
#pragma unroll
        for (int cc = 0; cc < 6; cc++) r[cc] = acc[oo][cc];
    }
}

// ---------------------------------------------------------------------------
// setup kernels
// ---------------------------------------------------------------------------
__global__ void k_initkeys()
{
    int i = blockIdx.x * blockDim.x + threadIdx.x;
    if (i < NSEG * 128) d_key1[i] = 0ull;
    if (i < NSEG * 256) d_key2[i] = 0ull;
}

struct TList {
    const float* src[7];
    int off[7];
};

// W[o][c] (OxC) -> d_wt[off + c*O + o]; one matrix per blockIdx.z
__global__ void k_tmany(TList tl, int O, int C)
{
    __shared__ float t[32][33];
    const float* src = tl.src[blockIdx.z];
    int dstOff = tl.off[blockIdx.z];
    int cb = blockIdx.x * 32, ob = blockIdx.y * 32;
    int x = threadIdx.x, y = threadIdx.y;
    for (int i = y; i < 32; i += 8) t[i][x] = src[(size_t)(ob + i) * C + cb + x];
    __syncthreads();
    for (int i = y; i < 32; i += 8) d_wt[dstOff + (size_t)(cb + i) * O + ob + x] = t[x][i];
}

// ---------------------------------------------------------------------------
// stage 1: vn1 -> vn2 -> vn3 -> (store g3, argmax over Wd1 dot)
// 32 points per CTA, 256 threads (16x16 map), KT=64
// smem: bufA [128][96] (48KB, in-place) + smW 2 slots x 2 x 64x128 (128KB) = 176KB
// ---------------------------------------------------------------------------
__global__ void __launch_bounds__(256, 1) k_stage1(const float* __restrict__ x,
                                                   const int* __restrict__ radius)
{
    extern __shared__ float sm[];
    float* bufA = sm;                 // [128][96]
    float* smW  = sm + 12288;
    int tid = threadIdx.x;
    int n0 = blockIdx.x * 32;

    // load X tile transposed: bufA[c][p*3+j] = x[n0+p][c][j]
    const float* xg = x + (size_t)n0 * 384;
    for (int i4 = tid; i4 < 3072; i4 += 256) {
        float4 v = ((const float4*)xg)[i4];
        int lin = i4 * 4;
        int p = lin / 384, r = lin % 384;
        float vv[4] = {v.x, v.y, v.z, v.w};
#pragma unroll
        for (int e = 0; e < 4; e++) {
            int rr = r + e;
            int c = rr / 3, j = rr - c * 3;
            bufA[c * 96 + p * 3 + j] = vv[e];
        }
    }

    int ty = tid >> 4, tx = tid & 15;
    int o_base = ty * 8, col_base = tx * 6;

    u64 aP[4][6], aD[4][6];
    float fP[8][6], fD[8][6];

    // L1: vn1  (mm ends with a barrier -> safe to overwrite bufA)
    zero_acc(aP); zero_acc(aD);
    mm_pair2<128, 128, 96, 64>(d_wt + O_W1F, d_wt + O_W1D, bufA, smW, aP, aD, o_base, col_base, tid);
    unpack_acc(aP, fP); unpack_acc(aD, fD);
    vn_combine(fP, fD);
    store_tile<96>(bufA, fP, o_base, col_base);

    // L2: vn2
    zero_acc(aP); zero_acc(aD);
    mm_pair2<128, 128, 96, 64>(d_wt + O_W2F, d_wt + O_W2D, bufA, smW, aP, aD, o_base, col_base, tid);
    unpack_acc(aP, fP); unpack_acc(aD, fD);
    vn_combine(fP, fD);
    store_tile<96>(bufA, fP, o_base, col_base);

    // L3: vn3
    zero_acc(aP);
    mm_one2<128, 128, 96, 64>(d_wt + O_W3, bufA, smW, aP, o_base, col_base, tid);
    unpack_acc(aP, fP);
    store_tile<96>(bufA, fP, o_base, col_base);

    // write g3 to global scratch (layout [c][n*3+j])
#pragma unroll
    for (int oo = 0; oo < 8; oo++) {
        float* g = d_g3s + (size_t)(o_base + oo) * NT3 + (size_t)n0 * 3 + col_base;
#pragma unroll
        for (int cc = 0; cc < 6; cc++) g[cc] = fP[oo][cc];
    }

    // L3d: d = Wd1 * Y   (bufA holds Y)
    zero_acc(aD);
    mm_one2<128, 128, 96, 64>(d_wt + O_WD1, bufA, smW, aD, o_base, col_base, tid);
    unpack_acc(aD, fD);

    // per-(channel,point) dot, argmax reduce across the CTA's 32 points
    int seg = radius[n0];
    unsigned int nA = (unsigned int)(n0 + 2 * tx);
#pragma unroll
    for (int oo = 0; oo < 8; oo++) {
        float dot0 = fP[oo][0] * fD[oo][0] + fP[oo][1] * fD[oo][1] + fP[oo][2] * fD[oo][2];
        float dot1 = fP[oo][3] * fD[oo][3] + fP[oo][4] * fD[oo][4] + fP[oo][5] * fD[oo][5];
        u64 b0 = packkey(dot0, nA);
        u64 b1 = packkey(dot1, nA + 1);
        u64 best = (b0 > b1) ? b0 : b1;
#pragma unroll
        for (int m = 1; m < 16; m <<= 1) {
            u64 o = shfl_xor_u64(best, m);
            if (o > best) best = o;
        }
        if (tx == 0) atomicMax(&d_key1[seg * 128 + o_base + oo], best);
    }
}

// ---------------------------------------------------------------------------
// gather + relu3  (one block per segment, 128 threads)
// ---------------------------------------------------------------------------
__global__ void k_relu3()
{
    __shared__ float G[128][3];
    int seg = blockIdx.x, c = threadIdx.x;
    u64 key = d_key1[seg * 128 + c];
    unsigned int idx = 0xFFFFFFFFu - (unsigned int)(key & 0xFFFFFFFFull);
    if (idx >= NPTS) idx = 0;
    float g0 = d_g3s[(size_t)c * NT3 + (size_t)idx * 3 + 0];
    float g1 = d_g3s[(size_t)c * NT3 + (size_t)idx * 3 + 1];
    float g2 = d_g3s[(size_t)c * NT3 + (size_t)idx * 3 + 2];
    G[c][0] = g0; G[c][1] = g1; G[c][2] = g2;
    __syncthreads();
    float a0 = 0.f, a1 = 0.f, a2 = 0.f;
    const float* w = d_wt + O_WR3;   // k-major: w[k*128 + c]
    for (int k = 0; k < 128; k++) {
        float ww = w[k * 128 + c];
        a0 += ww * G[k][0]; a1 += ww * G[k][1]; a2 += ww * G[k][2];
    }
    float dot = g0 * a0 + g1 * a1 + g2 * a2;
    float dn  = a0 * a0 + a1 * a1 + a2 * a2;
    float o0 = g0, o1 = g1, o2 = g2;
    if (dot < 0.f) {
        float s = dot / (dn + EPSV);
        o0 -= s * a0; o1 -= s * a1; o2 -= s * a2;
    }
    d_r3[seg * 384 + c * 3 + 0] = o0;
    d_r3[seg * 384 + c * 3 + 1] = o1;
    d_r3[seg * 384 + c * 3 + 2] = o2;
}

// ---------------------------------------------------------------------------
// stage 2: concat -> vn4 -> vn5 -> (store h5, argmax over Wd2 dot)
// 16 points per CTA, 256 threads (32x8 map), pair KT=32, one KT=64
// smem: bufA [256][48] (48KB) + smW 128KB = 176KB
// ---------------------------------------------------------------------------
__global__ void __launch_bounds__(256, 1) k_stage2(const float* __restrict__ x,
                                                   const int* __restrict__ radius)
{
    extern __shared__ float sm[];
    float* bufA = sm;                 // [256][48]
    float* smW  = sm + 12288;
    int tid = threadIdx.x;
    int n0 = blockIdx.x * 16;
    int seg = radius[n0];

    // x part: bufA[c][p*3+j] = x[n0+p][c][j], c < 128
    const float* xg = x + (size_t)n0 * 384;
    for (int i4 = tid; i4 < 1536; i4 += 256) {
        float4 v = ((const float4*)xg)[i4];
        int lin = i4 * 4;
        int p = lin / 384, r = lin % 384;
        float vv[4] = {v.x, v.y, v.z, v.w};
#pragma unroll
        for (int e = 0; e < 4; e++) {
            int rr = r + e;
            int c = rr / 3, j = rr - c * 3;
            bufA[c * 48 + p * 3 + j] = vv[e];
        }
    }
    // r3 broadcast part: bufA[128+c][p*3+j] = r3[seg][c][j]
    const float* r3s = d_r3 + seg * 384;
    for (int i = tid; i < 128 * 48; i += 256) {
        int c = i / 48, col = i - c * 48;
        int j = col % 3;
        bufA[(128 + c) * 48 + col] = r3s[c * 3 + j];
    }

    int ty = tid >> 3, tx = tid & 7;
    int o_base = ty * 8, col_base = tx * 6;

    u64 aP[4][6], aD[4][6];
    float fP[8][6], fD[8][6];

    // L4: vn4
    zero_acc(aP); zero_acc(aD);
    mm_pair2<256, 256, 48, 32>(d_wt + O_W4F, d_wt + O_W4D, bufA, smW, aP, aD, o_base, col_base, tid);
    unpack_acc(aP, fP); unpack_acc(aD, fD);
    vn_combine(fP, fD);
    store_tile<48>(bufA, fP, o_base, col_base);

    // L5: vn5
    zero_acc(aP);
    mm_one2<256, 256, 48, 64>(d_wt + O_W5, bufA, smW, aP, o_base, col_base, tid);
    unpack_acc(aP, fP);
    store_tile<48>(bufA, fP, o_base, col_base);

    // write h5 scratch (layout [c][n*3+j])
#pragma unroll
    for (int oo = 0; oo < 8; oo++) {
        float* g = d_h5s + (size_t)(o_base + oo) * NT3 + (size_t)n0 * 3 + col_base;
#pragma unroll
        for (int cc = 0; cc < 6; cc++) g[cc] = fP[oo][cc];
    }

    // L5d: d = Wd2 * Y   (bufA holds Y)
    zero_acc(aD);
    mm_one2<256, 256, 48, 64>(d_wt + O_WD2, bufA, smW, aD, o_base, col_base, tid);
    unpack_acc(aD, fD);

    unsigned int nA = (unsigned int)(n0 + 2 * tx);
#pragma unroll
    for (int oo = 0; oo < 8; oo++) {
        float dot0 = fP[oo][0] * fD[oo][0] + fP[oo][1] * fD[oo][1] + fP[oo][2] * fD[oo][2];
        float dot1 = fP[oo][3] * fD[oo][3] + fP[oo][4] * fD[oo][4] + fP[oo][5] * fD[oo][5];
        u64 b0 = packkey(dot0, nA);
        u64 b1 = packkey(dot1, nA + 1);
        u64 best = (b0 > b1) ? b0 : b1;
#pragma unroll
        for (int m = 1; m < 8; m <<= 1) {
            u64 o = shfl_xor_u64(best, m);
            if (o > best) best = o;
        }
        if (tx == 0) atomicMax(&d_key2[seg * 256 + o_base + oo], best);
    }
}

// ---------------------------------------------------------------------------
// gather + relu5 -> output  (one block per segment, 256 threads)
// ---------------------------------------------------------------------------
__global__ void k_relu5(float* __restrict__ out)
{
    __shared__ float G[256][3];
    int seg = blockIdx.x, c = threadIdx.x;
    u64 key = d_key2[seg * 256 + c];
    unsigned int idx = 0xFFFFFFFFu - (unsigned int)(key & 0xFFFFFFFFull);
    if (idx >= NPTS) idx = 0;
    float g0 = d_h5s[(size_t)c * NT3 + (size_t)idx * 3 + 0];
    float g1 = d_h5s[(size_t)c * NT3 + (size_t)idx * 3 + 1];
    float g2 = d_h5s[(size_t)c * NT3 + (size_t)idx * 3 + 2];
    G[c][0] = g0; G[c][1] = g1; G[c][2] = g2;
    __syncthreads();
    float a0 = 0.f, a1 = 0.f, a2 = 0.f;
    const float* w = d_wt + O_WR5;   // k-major: w[k*256 + c]
    for (int k = 0; k < 256; k++) {
        float ww = w[k * 256 + c];
        a0 += ww * G[k][0]; a1 += ww * G[k][1]; a2 += ww * G[k][2];
    }
    float dot = g0 * a0 + g1 * a1 + g2 * a2;
    float dn  = a0 * a0 + a1 * a1 + a2 * a2;
    float o0 = g0, o1 = g1, o2 = g2;
    if (dot < 0.f) {
        float s = dot / (dn + EPSV);
        o0 -= s * a0; o1 -= s * a1; o2 -= s * a2;
    }
    out[seg * 768 + c * 3 + 0] = o0;
    out[seg * 768 + c * 3 + 1] = o1;
    out[seg * 768 + c * 3 + 2] = o2;
}

// ---------------------------------------------------------------------------
// host launcher
// ---------------------------------------------------------------------------
extern "C" void kernel_launch(void* const* d_in, const int* in_sizes, int n_in,
                              void* d_out, int out_size)
{
    const float* x      = (const float*)d_in[0];
    const int*   radius = (const int*)d_in[1];

    cudaFuncSetAttribute(k_stage1, cudaFuncAttributeMaxDynamicSharedMemorySize, 180224);
    cudaFuncSetAttribute(k_stage2, cudaFuncAttributeMaxDynamicSharedMemorySize, 180224);

    k_initkeys<<<32, 256>>>();

    dim3 tb(32, 8);
    TList t128;
    t128.src[0] = (const float*)d_in[2];  t128.off[0] = O_W1F;
    t128.src[1] = (const float*)d_in[3];  t128.off[1] = O_W1D;
    t128.src[2] = (const float*)d_in[4];  t128.off[2] = O_W2F;
    t128.src[3] = (const float*)d_in[5];  t128.off[3] = O_W2D;
    t128.src[4] = (const float*)d_in[6];  t128.off[4] = O_W3;
    t128.src[5] = (const float*)d_in[7];  t128.off[5] = O_WD1;
    t128.src[6] = (const float*)d_in[8];  t128.off[6] = O_WR3;
    k_tmany<<<dim3(4, 4, 7), tb>>>(t128, 128, 128);

    TList t256;
    t256.src[0] = (const float*)d_in[9];   t256.off[0] = O_W4F;
    t256.src[1] = (const float*)d_in[10];  t256.off[1] = O_W4D;
    t256.src[2] = (const float*)d_in[11];  t256.off[2] = O_W5;
    t256.src[3] = (const float*)d_in[12];  t256.off[3] = O_WD2;
    t256.src[4] = (const float*)d_in[13];  t256.off[4] = O_WR5;
    t256.src[5] = t256.src[4];             t256.off[5] = O_WR5;  // unused (grid.z=5)
    t256.src[6] = t256.src[4];             t256.off[6] = O_WR5;
    k_tmany<<<dim3(8, 8, 5), tb>>>(t256, 256, 256);

    k_stage1<<<NPTS / 32, 256, 180224>>>(x, radius);
    k_relu3<<<NSEG, 128>>>();
    k_stage2<<<NPTS / 16, 256, 180224>>>(x, radius);
    k_relu5<<<NSEG, 256>>>((float*)d_out);
}

// round 9
// speedup vs baseline: 1.1175x; 1.0141x over previous
#include <cuda_runtime.h>

#define EPSV 1e-7f
#define NPTS 131072
#define NT3  393216        // NPTS*3
#define NSEG 32

// ---- transposed-weight offsets (in floats) within d_wt ----
#define O_W1F 0
#define O_W1D 16384
#define O_W2F 32768
#define O_W2D 49152
#define O_W3  65536
#define O_WD1 81920
#define O_WR3 98304
#define O_W4F 114688
#define O_W4D 180224
#define O_W5  245760
#define O_WD2 311296
#define O_WR5 376832
#define WT_TOTAL 442368

// ---- static device scratch (no allocations allowed) ----
__device__ float d_wt[WT_TOTAL];
__device__ float d_g3s[128ull * (unsigned long long)NT3];   // vn3 output, layout [c][n*3+j]
__device__ float d_h5s[256ull * (unsigned long long)NT3];   // vn5 output, layout [c][n*3+j]
__device__ float d_r3[NSEG * 128 * 3];                      // relu3 output per segment
__device__ unsigned long long d_key1[NSEG * 128];
__device__ unsigned long long d_key2[NSEG * 256];

typedef unsigned long long u64;

// ---------------------------------------------------------------------------
// helpers
// ---------------------------------------------------------------------------
__device__ __forceinline__ u64 packkey(float dot, unsigned int n) {
    unsigned int u = __float_as_uint(dot);
    u = (u & 0x80000000u) ? ~u : (u | 0x80000000u);   // order-preserving float->uint
    return ((u64)u << 32) | (u64)(0xFFFFFFFFu - n);   // tie -> min n
}

__device__ __forceinline__ u64 shfl_xor_u64(u64 v, int m) {
    unsigned int lo = (unsigned int)v;
    unsigned int hi = (unsigned int)(v >> 32);
    lo = __shfl_xor_sync(0xFFFFFFFFu, lo, m);
    hi = __shfl_xor_sync(0xFFFFFFFFu, hi, m);
    return ((u64)hi << 32) | lo;
}

// packed fp32x2 FMA: d = a * b + d (lanewise, exact fp32 per lane)
__device__ __forceinline__ void ffma2(u64& d, u64 a, u64 b) {
    asm("fma.rn.f32x2 %0, %1, %2, %0;" : "+l"(d) : "l"(a), "l"(b));
}
__device__ __forceinline__ u64 packdup(float x) {
    u64 r;
    asm("mov.b64 %0, {%1, %1};" : "=l"(r) : "r"(__float_as_uint(x)));
    return r;
}
__device__ __forceinline__ void unpack2(u64 v, float& lo, float& hi) {
    unsigned int l, h;
    asm("mov.b64 {%0, %1}, %2;" : "=r"(l), "=r"(h) : "l"(v));
    lo = __uint_as_float(l);
    hi = __uint_as_float(h);
}

// cp.async 16B helpers
__device__ __forceinline__ void cpa16(float* smdst, const float4* gsrc) {
    unsigned s = (unsigned)__cvta_generic_to_shared(smdst);
    asm volatile("cp.async.cg.shared.global [%0], [%1], 16;" :: "r"(s), "l"(gsrc));
}
__device__ __forceinline__ void cp_commit() { asm volatile("cp.async.commit_group;"); }
__device__ __forceinline__ void cp_wait1() { asm volatile("cp.async.wait_group 1;" ::: "memory"); }
__device__ __forceinline__ void cp_wait0() { asm volatile("cp.async.wait_group 0;" ::: "memory"); }

// ---------------------------------------------------------------------------
// matmul cores (R4 structure). Thread tile 8 channels (4 packed pairs) x 6 cols.
// wT k-major: wT[k*OTOT + o]. smW: double-buffered cp.async weight staging.
// kk loops unrolled x8 only: keeps each mm body ~8KB so all inner loops stay
// resident in L1.5 I$ (full unroll streamed ~100KB of code per stage kernel).
// ---------------------------------------------------------------------------
template<int K, int OTOT, int COLS, int KT>
__device__ __forceinline__ void mm_pair2(const float* __restrict__ wfT, const float* __restrict__ wdT,
                                         const float* __restrict__ bufIn, float* smW,
                                         u64 accP[4][6], u64 accD[4][6],
                                         int o_base, int col_base, int tid)
{
    constexpr int TW    = KT * OTOT;
    constexpr int BUFSZ = 2 * TW;
    constexpr int NT    = K / KT;
    constexpr int PER   = TW / 4 / 256;

    {
        const float4* sf = (const float4*)(wfT);
        const float4* sd = (const float4*)(wdT);
#pragma unroll
        for (int r = 0; r < PER; r++) {
            cpa16(smW +      (tid + 256 * r) * 4, sf + tid + 256 * r);
            cpa16(smW + TW + (tid + 256 * r) * 4, sd + tid + 256 * r);
        }
        cp_commit();
    }
    for (int t = 0; t < NT; t++) {
        if (t + 1 < NT) {
            float* df = smW + ((t + 1) & 1) * BUFSZ;
            float* dd = df + TW;
            const float4* sf = (const float4*)(wfT + (t + 1) * KT * OTOT);
            const float4* sd = (const float4*)(wdT + (t + 1) * KT * OTOT);
#pragma unroll
            for (int r = 0; r < PER; r++) {
                cpa16(df + (tid + 256 * r) * 4, sf + tid + 256 * r);
                cpa16(dd + (tid + 256 * r) * 4, sd + tid + 256 * r);
            }
            cp_commit();
            cp_wait1();
        } else {
            cp_wait0();
        }
        __syncthreads();
        const float* Wf = smW + (t & 1) * BUFSZ;
        const float* Wd = Wf + TW;
#pragma unroll 8
        for (int kk = 0; kk < KT; kk++) {
            const ulonglong2* ar = (const ulonglong2*)(Wf + kk * OTOT + o_base);
            const ulonglong2* dr = (const ulonglong2*)(Wd + kk * OTOT + o_base);
            const float* br = bufIn + (t * KT + kk) * COLS + col_base;
            float2 b01 = *(const float2*)(br);
            float2 b23 = *(const float2*)(br + 2);
            float2 b45 = *(const float2*)(br + 4);
            u64 b2[6];
            b2[0] = packdup(b01.x); b2[1] = packdup(b01.y);
            b2[2] = packdup(b23.x); b2[3] = packdup(b23.y);
            b2[4] = packdup(b45.x); b2[5] = packdup(b45.y);
            ulonglong2 af0 = ar[0], af1 = ar[1], ad0 = dr[0], ad1 = dr[1];
            u64 a2f[4] = {af0.x, af0.y, af1.x, af1.y};
            u64 a2d[4] = {ad0.x, ad0.y, ad1.x, ad1.y};
#pragma unroll
            for (int op = 0; op < 4; op++)
#pragma unroll
                for (int cc = 0; cc < 6; cc++) {
                    ffma2(accP[op][cc], a2f[op], b2[cc]);
                    ffma2(accD[op][cc], a2d[op], b2[cc]);
                }
        }
        __syncthreads();
    }
}

template<int K, int OTOT, int COLS, int KT>
__device__ __forceinline__ void mm_one2(const float* __restrict__ wT,
                                        const float* __restrict__ bufIn, float* smW,
                                        u64 acc[4][6], int o_base, int col_base, int tid)
{
    constexpr int TW  = KT * OTOT;
    constexpr int NT  = K / KT;
    constexpr int PER = TW / 4 / 256;

    {
        const float4* sf = (const float4*)(wT);
#pragma unroll
        for (int r = 0; r < PER; r++)
            cpa16(smW + (tid + 256 * r) * 4, sf + tid + 256 * r);
        cp_commit();
    }
    for (int t = 0; t < NT; t++) {
        if (t + 1 < NT) {
            float* df = smW + ((t + 1) & 1) * TW;
            const float4* sf = (const float4*)(wT + (t + 1) * KT * OTOT);
#pragma unroll
            for (int r = 0; r < PER; r++)
                cpa16(df + (tid + 256 * r) * 4, sf + tid + 256 * r);
            cp_commit();
            cp_wait1();
        } else {
            cp_wait0();
        }
        __syncthreads();
        const float* Wf = smW + (t & 1) * TW;
#pragma unroll 8
        for (int kk = 0; kk < KT; kk++) {
            const ulonglong2* ar = (const ulonglong2*)(Wf + kk * OTOT + o_base);
            const float* br = bufIn + (t * KT + kk) * COLS + col_base;
            float2 b01 = *(const float2*)(br);
            float2 b23 = *(const float2*)(br + 2);
            float2 b45 = *(const float2*)(br + 4);
            u64 b2[6];
            b2[0] = packdup(b01.x); b2[1] = packdup(b01.y);
            b2[2] = packdup(b23.x); b2[3] = packdup(b23.y);
            b2[4] = packdup(b45.x); b2[5] = packdup(b45.y);
            ulonglong2 af0 = ar[0], af1 = ar[1];
            u64 a2[4] = {af0.x, af0.y, af1.x, af1.y};
#pragma unroll
            for (int op = 0; op < 4; op++)
#pragma unroll
                for (int cc = 0; cc < 6; cc++)
                    ffma2(acc[op][cc], a2[op], b2[cc]);
        }
        __syncthreads();
    }
}

__device__ __forceinline__ void zero_acc(u64 a[4][6]) {
#pragma unroll
    for (int op = 0; op < 4; op++)
#pragma unroll
        for (int cc = 0; cc < 6; cc++) a[op][cc] = 0ull;
}

__device__ __forceinline__ void unpack_acc(const u64 a[4][6], float f[8][6]) {
#pragma unroll
    for (int op = 0; op < 4; op++)
#pragma unroll
        for (int cc = 0; cc < 6; cc++)
            unpack2(a[op][cc], f[2 * op][cc], f[2 * op + 1][cc]);
}

// VN LeakyReLU (ns=0): keep p where dot>=0 else p - dot/(dn+eps)*d. 8 ch x 2 points.
__device__ __forceinline__ void vn_combine(float accP[8][6], float accD[8][6])
{
#pragma unroll
    for (int oo = 0; oo < 8; oo++)
#pragma unroll
        for (int p = 0; p < 2; p++) {
            float p0 = accP[oo][3 * p], p1 = accP[oo][3 * p + 1], p2 = accP[oo][3 * p + 2];
            float q0 = accD[oo][3 * p], q1 = accD[oo][3 * p + 1], q2 = accD[oo][3 * p + 2];
            float dot = p0 * q0 + p1 * q1 + p2 * q2;
            float dn  = q0 * q0 + q1 * q1 + q2 * q2;
            if (dot < 0.f) {
                float s = dot / (dn + EPSV);
                accP[oo][3 * p]     = p0 - s * q0;
                accP[oo][3 * p + 1] = p1 - s * q1;
                accP[oo][3 * p + 2] = p2 - s * q2;
            }
        }
}

template<int COLS>
__device__ __forceinline__ void store_tile(float* buf, float acc[8][6], int o_base, int col_base)
{
#pragma unroll
    for (int oo = 0; oo < 8; oo++) {
        float* r = buf + (o_base + oo) * COLS + col_base;
#pragma unroll
        for (int cc = 0; cc < 6; cc++) r[cc] = acc[oo][cc];
    }
}

// ---------------------------------------------------------------------------
// setup kernels
// ---------------------------------------------------------------------------
__global__ void k_initkeys()
{
    int i = blockIdx.x * blockDim.x + threadIdx.x;
    if (i < NSEG * 128) d_key1[i] = 0ull;
    if (i < NSEG * 256) d_key2[i] = 0ull;
}

struct TList {
    const float* src[7];
    int off[7];
};

// W[o][c] (OxC) -> d_wt[off + c*O + o]; one matrix per blockIdx.z
__global__ void k_tmany(TList tl, int O, int C)
{
    __shared__ float t[32][33];
    const float* src = tl.src[blockIdx.z];
    int dstOff = tl.off[blockIdx.z];
    int cb = blockIdx.x * 32, ob = blockIdx.y * 32;
    int x = threadIdx.x, y = threadIdx.y;
    for (int i = y; i < 32; i += 8) t[i][x] = src[(size_t)(ob + i) * C + cb + x];
    __syncthreads();
    for (int i = y; i < 32; i += 8) d_wt[dstOff + (size_t)(cb + i) * O + ob + x] = t[x][i];
}

// ---------------------------------------------------------------------------
// stage 1: vn1 -> vn2 -> vn3 -> (store g3, argmax over Wd1 dot)
// 32 points per CTA, 256 threads (16x16 map), KT=32
// smem: bufA [128][96] (48KB, in-place reused) + smW 4*32*128 floats (64KB) = 112KB
// ---------------------------------------------------------------------------
__global__ void __launch_bounds__(256, 1) k_stage1(const float* __restrict__ x,
                                                   const int* __restrict__ radius)
{
    extern __shared__ float sm[];
    float* bufA = sm;                 // [128][96]
    float* smW  = sm + 12288;         // 4 x [32][128] (double-buffered f+d)
    int tid = threadIdx.x;
    int n0 = blockIdx.x * 32;

    // load X tile transposed: bufA[c][p*3+j] = x[n0+p][c][j]
    const float* xg = x + (size_t)n0 * 384;
    for (int i4 = tid; i4 < 3072; i4 += 256) {
        float4 v = ((const float4*)xg)[i4];
        int lin = i4 * 4;
        int p = lin / 384, r = lin % 384;
        float vv[4] = {v.x, v.y, v.z, v.w};
#pragma unroll
        for (int e = 0; e < 4; e++) {
            int rr = r + e;
            int c = rr / 3, j = rr - c * 3;
            bufA[c * 96 + p * 3 + j] = vv[e];
        }
    }

    int ty = tid >> 4, tx = tid & 15;
    int o_base = ty * 8, col_base = tx * 6;

    u64 aP[4][6], aD[4][6];
    float fP[8][6], fD[8][6];

    // L1: vn1  (mm ends with a barrier -> safe to overwrite bufA)
    zero_acc(aP); zero_acc(aD);
    mm_pair2<128, 128, 96, 32>(d_wt + O_W1F, d_wt + O_W1D, bufA, smW, aP, aD, o_base, col_base, tid);
    unpack_acc(aP, fP); unpack_acc(aD, fD);
    vn_combine(fP, fD);
    store_tile<96>(bufA, fP, o_base, col_base);

    // L2: vn2
    zero_acc(aP); zero_acc(aD);
    mm_pair2<128, 128, 96, 32>(d_wt + O_W2F, d_wt + O_W2D, bufA, smW, aP, aD, o_base, col_base, tid);
    unpack_acc(aP, fP); unpack_acc(aD, fD);
    vn_combine(fP, fD);
    store_tile<96>(bufA, fP, o_base, col_base);

    // L3: vn3
    zero_acc(aP);
    mm_one2<128, 128, 96, 32>(d_wt + O_W3, bufA, smW, aP, o_base, col_base, tid);
    unpack_acc(aP, fP);
    store_tile<96>(bufA, fP, o_base, col_base);

    // write g3 to global scratch (layout [c][n*3+j])
#pragma unroll
    for (int oo = 0; oo < 8; oo++) {
        float* g = d_g3s + (size_t)(o_base + oo) * NT3 + (size_t)n0 * 3 + col_base;
#pragma unroll
        for (int cc = 0; cc < 6; cc++) g[cc] = fP[oo][cc];
    }

    // L3d: d = Wd1 * Y   (bufA holds Y)
    zero_acc(aD);
    mm_one2<128, 128, 96, 32>(d_wt + O_WD1, bufA, smW, aD, o_base, col_base, tid);
    unpack_acc(aD, fD);

    // per-(channel,point) dot, argmax reduce across the CTA's 32 points
    int seg = radius[n0];
    unsigned int nA = (unsigned int)(n0 + 2 * tx);
#pragma unroll
    for (int oo = 0; oo < 8; oo++) {
        float dot0 = fP[oo][0] * fD[oo][0] + fP[oo][1] * fD[oo][1] + fP[oo][2] * fD[oo][2];
        float dot1 = fP[oo][3] * fD[oo][3] + fP[oo][4] * fD[oo][4] + fP[oo][5] * fD[oo][5];
        u64 b0 = packkey(dot0, nA);
        u64 b1 = packkey(dot1, nA + 1);
        u64 best = (b0 > b1) ? b0 : b1;
#pragma unroll
        for (int m = 1; m < 16; m <<= 1) {
            u64 o = shfl_xor_u64(best, m);
            if (o > best) best = o;
        }
        if (tx == 0) atomicMax(&d_key1[seg * 128 + o_base + oo], best);
    }
}

// ---------------------------------------------------------------------------
// gather + relu3  (one block per segment, 128 threads)
// ---------------------------------------------------------------------------
__global__ void k_relu3()
{
    __shared__ float G[128][3];
    int seg = blockIdx.x, c = threadIdx.x;
    u64 key = d_key1[seg * 128 + c];
    unsigned int idx = 0xFFFFFFFFu - (unsigned int)(key & 0xFFFFFFFFull);
    if (idx >= NPTS) idx = 0;
    float g0 = d_g3s[(size_t)c * NT3 + (size_t)idx * 3 + 0];
    float g1 = d_g3s[(size_t)c * NT3 + (size_t)idx * 3 + 1];
    float g2 = d_g3s[(size_t)c * NT3 + (size_t)idx * 3 + 2];
    G[c][0] = g0; G[c][1] = g1; G[c][2] = g2;
    __syncthreads();
    float a0 = 0.f, a1 = 0.f, a2 = 0.f;
    const float* w = d_wt + O_WR3;   // k-major: w[k*128 + c]
    for (int k = 0; k < 128; k++) {
        float ww = w[k * 128 + c];
        a0 += ww * G[k][0]; a1 += ww * G[k][1]; a2 += ww * G[k][2];
    }
    float dot = g0 * a0 + g1 * a1 + g2 * a2;
    float dn  = a0 * a0 + a1 * a1 + a2 * a2;
    float o0 = g0, o1 = g1, o2 = g2;
    if (dot < 0.f) {
        float s = dot / (dn + EPSV);
        o0 -= s * a0; o1 -= s * a1; o2 -= s * a2;
    }
    d_r3[seg * 384 + c * 3 + 0] = o0;
    d_r3[seg * 384 + c * 3 + 1] = o1;
    d_r3[seg * 384 + c * 3 + 2] = o2;
}

// ---------------------------------------------------------------------------
// stage 2: concat -> vn4 -> vn5 -> (store h5, argmax over Wd2 dot)
// 16 points per CTA, 256 threads (32x8 map), KT=32
// smem: bufA [256][48] (48KB, in-place) + smW 4*32*256 floats (128KB) = 176KB
// ---------------------------------------------------------------------------
__global__ void __launch_bounds__(256, 1) k_stage2(const float* __restrict__ x,
                                                   const int* __restrict__ radius)
{
    extern __shared__ float sm[];
    float* bufA = sm;                 // [256][48]
    float* smW  = sm + 12288;         // 4 x [32][256]
    int tid = threadIdx.x;
    int n0 = blockIdx.x * 16;
    int seg = radius[n0];

    // x part: bufA[c][p*3+j] = x[n0+p][c][j], c < 128
    const float* xg = x + (size_t)n0 * 384;
    for (int i4 = tid; i4 < 1536; i4 += 256) {
        float4 v = ((const float4*)xg)[i4];
        int lin = i4 * 4;
        int p = lin / 384, r = lin % 384;
        float vv[4] = {v.x, v.y, v.z, v.w};
#pragma unroll
        for (int e = 0; e < 4; e++) {
            int rr = r + e;
            int c = rr / 3, j = rr - c * 3;
            bufA[c * 48 + p * 3 + j] = vv[e];
        }
    }
    // r3 broadcast part: bufA[128+c][p*3+j] = r3[seg][c][j]
    const float* r3s = d_r3 + seg * 384;
    for (int i = tid; i < 128 * 48; i += 256) {
        int c = i / 48, col = i - c * 48;
        int j = col % 3;
        bufA[(128 + c) * 48 + col] = r3s[c * 3 + j];
    }

    int ty = tid >> 3, tx = tid & 7;
    int o_base = ty * 8, col_base = tx * 6;

    u64 aP[4][6], aD[4][6];
    float fP[8][6], fD[8][6];

    // L4: vn4
    zero_acc(aP); zero_acc(aD);
    mm_pair2<256, 256, 48, 32>(d_wt + O_W4F, d_wt + O_W4D, bufA, smW, aP, aD, o_base, col_base, tid);
    unpack_acc(aP, fP); unpack_acc(aD, fD);
    vn_combine(fP, fD);
    store_tile<48>(bufA, fP, o_base, col_base);

    // L5: vn5
    zero_acc(aP);
    mm_one2<256, 256, 48, 32>(d_wt + O_W5, bufA, smW, aP, o_base, col_base, tid);
    unpack_acc(aP, fP);
    store_tile<48>(bufA, fP, o_base, col_base);

    // write h5 scratch (layout [c][n*3+j])
#pragma unroll
    for (int oo = 0; oo < 8; oo++) {
        float* g = d_h5s + (size_t)(o_base + oo) * NT3 + (size_t)n0 * 3 + col_base;
#pragma unroll
        for (int cc = 0; cc < 6; cc++) g[cc] = fP[oo][cc];
    }

    // L5d: d = Wd2 * Y   (bufA holds Y)
    zero_acc(aD);
    mm_one2<256, 256, 48, 32>(d_wt + O_WD2, bufA, smW, aD, o_base, col_base, tid);
    unpack_acc(aD, fD);

    unsigned int nA = (unsigned int)(n0 + 2 * tx);
#pragma unroll
    for (int oo = 0; oo < 8; oo++) {
        float dot0 = fP[oo][0] * fD[oo][0] + fP[oo][1] * fD[oo][1] + fP[oo][2] * fD[oo][2];
        float dot1 = fP[oo][3] * fD[oo][3] + fP[oo][4] * fD[oo][4] + fP[oo][5] * fD[oo][5];
        u64 b0 = packkey(dot0, nA);
        u64 b1 = packkey(dot1, nA + 1);
        u64 best = (b0 > b1) ? b0 : b1;
#pragma unroll
        for (int m = 1; m < 8; m <<= 1) {
            u64 o = shfl_xor_u64(best, m);
            if (o > best) best = o;
        }
        if (tx == 0) atomicMax(&d_key2[seg * 256 + o_base + oo], best);
    }
}

// ---------------------------------------------------------------------------
// gather + relu5 -> output  (one block per segment, 256 threads)
// ---------------------------------------------------------------------------
__global__ void k_relu5(float* __restrict__ out)
{
    __shared__ float G[256][3];
    int seg = blockIdx.x, c = threadIdx.x;
    u64 key = d_key2[seg * 256 + c];
    unsigned int idx = 0xFFFFFFFFu - (unsigned int)(key & 0xFFFFFFFFull);
    if (idx >= NPTS) idx = 0;
    float g0 = d_h5s[(size_t)c * NT3 + (size_t)idx * 3 + 0];
    float g1 = d_h5s[(size_t)c * NT3 + (size_t)idx * 3 + 1];
    float g2 = d_h5s[(size_t)c * NT3 + (size_t)idx * 3 + 2];
    G[c][0] = g0; G[c][1] = g1; G[c][2] = g2;
    __syncthreads();
    float a0 = 0.f, a1 = 0.f, a2 = 0.f;
    const float* w = d_wt + O_WR5;   // k-major: w[k*256 + c]
    for (int k = 0; k < 256; k++) {
        float ww = w[k * 256 + c];
        a0 += ww * G[k][0]; a1 += ww * G[k][1]; a2 += ww * G[k][2];
    }
    float dot = g0 * a0 + g1 * a1 + g2 * a2;
    float dn  = a0 * a0 + a1 * a1 + a2 * a2;
    float o0 = g0, o1 = g1, o2 = g2;
    if (dot < 0.f) {
        float s = dot / (dn + EPSV);
        o0 -= s * a0; o1 -= s * a1; o2 -= s * a2;
    }
    out[seg * 768 + c * 3 + 0] = o0;
    out[seg * 768 + c * 3 + 1] = o1;
    out[seg * 768 + c * 3 + 2] = o2;
}

// ---------------------------------------------------------------------------
// host launcher
// ---------------------------------------------------------------------------
extern "C" void kernel_launch(void* const* d_in, const int* in_sizes, int n_in,
                              void* d_out, int out_size)
{
    const float* x      = (const float*)d_in[0];
    const int*   radius = (const int*)d_in[1];

    cudaFuncSetAttribute(k_stage1, cudaFuncAttributeMaxDynamicSharedMemorySize, 114688);
    cudaFuncSetAttribute(k_stage2, cudaFuncAttributeMaxDynamicSharedMemorySize, 180224);

    k_initkeys<<<32, 256>>>();

    dim3 tb(32, 8);
    TList t128;
    t128.src[0] = (const float*)d_in[2];  t128.off[0] = O_W1F;
    t128.src[1] = (const float*)d_in[3];  t128.off[1] = O_W1D;
    t128.src[2] = (const float*)d_in[4];  t128.off[2] = O_W2F;
    t128.src[3] = (const float*)d_in[5];  t128.off[3] = O_W2D;
    t128.src[4] = (const float*)d_in[6];  t128.off[4] = O_W3;
    t128.src[5] = (const float*)d_in[7];  t128.off[5] = O_WD1;
    t128.src[6] = (const float*)d_in[8];  t128.off[6] = O_WR3;
    k_tmany<<<dim3(4, 4, 7), tb>>>(t128, 128, 128);

    TList t256;
    t256.src[0] = (const float*)d_in[9];   t256.off[0] = O_W4F;
    t256.src[1] = (const float*)d_in[10];  t256.off[1] = O_W4D;
    t256.src[2] = (const float*)d_in[11];  t256.off[2] = O_W5;
    t256.src[3] = (const float*)d_in[12];  t256.off[3] = O_WD2;
    t256.src[4] = (const float*)d_in[13];  t256.off[4] = O_WR5;
    t256.src[5] = t256.src[4];             t256.off[5] = O_WR5;  // unused (grid.z=5)
    t256.src[6] = t256.src[4];             t256.off[6] = O_WR5;
    k_tmany<<<dim3(8, 8, 5), tb>>>(t256, 256, 256);

    k_stage1<<<NPTS / 32, 256, 114688>>>(x, radius);
    k_relu3<<<NSEG, 128>>>();
    k_stage2<<<NPTS / 16, 256, 180224>>>(x, radius);
    k_relu5<<<NSEG, 256>>>((float*)d_out);
}

// round 11
// speedup vs baseline: 1.1642x; 1.0417x over previous
#include <cuda_runtime.h>

#define EPSV 1e-7f
#define NPTS 131072
#define NT3  393216
#define NSEG 32

#define O_W1F 0
#define O_W1D 16384
#define O_W2F 32768
#define O_W2D 49152
#define O_W3  65536
#define O_WD1 81920
#define O_WR3 98304
#define O_W4F 114688
#define O_W4D 180224
#define O_W5  245760
#define O_WD2 311296
#define O_WR5 376832
#define WT_TOTAL 442368

__device__ float d_wt[WT_TOTAL];
__device__ float d_g3s[128ull * (unsigned long long)NT3];
__device__ float d_h5s[256ull * (unsigned long long)NT3];
__device__ float d_r3[NSEG * 128 * 3];
__device__ unsigned long long d_key1[NSEG * 128];
__device__ unsigned long long d_key2[NSEG * 256];

typedef unsigned long long u64;

__device__ __forceinline__ u64 packkey(float dot, unsigned int n) {
    unsigned int u = __float_as_uint(dot);
    u = (u & 0x80000000u) ? ~u : (u | 0x80000000u);
    return ((u64)u << 32) | (u64)(0xFFFFFFFFu - n);
}

__device__ __forceinline__ void ffma2(u64& d, u64 a, u64 b) {
    asm("fma.rn.f32x2 %0, %1, %2, %0;" : "+l"(d) : "l"(a), "l"(b));
}
__device__ __forceinline__ u64 packdup(float x) {
    u64 r;
    asm("mov.b64 %0, {%1, %1};" : "=l"(r) : "r"(__float_as_uint(x)));
    return r;
}
__device__ __forceinline__ void unpack2(u64 v, float& lo, float& hi) {
    unsigned int l, h;
    asm("mov.b64 {%0, %1}, %2;" : "=r"(l), "=r"(h) : "l"(v));
    lo = __uint_as_float(l);
    hi = __uint_as_float(h);
}

__device__ __forceinline__ void cpa16(float* smdst, const float4* gsrc) {
    unsigned s = (unsigned)__cvta_generic_to_shared(smdst);
    asm volatile("cp.async.cg.shared.global [%0], [%1], 16;" :: "r"(s), "l"(gsrc));
}
__device__ __forceinline__ void cp_commit() { asm volatile("cp.async.commit_group;"); }
__device__ __forceinline__ void cp_wait1() { asm volatile("cp.async.wait_group 1;" ::: "memory"); }
__device__ __forceinline__ void cp_wait0() { asm volatile("cp.async.wait_group 0;" ::: "memory"); }

// ---------------------------------------------------------------------------
// matmul cores. Thread tile 8 channels (4 packed pairs) x 6 cols (2 points).
// Identical inner loop to the R4 optimum; NTH parametrizes thread count and
// weight cp.async staging uses a strided loop (NTH need not divide TW/4).
// ---------------------------------------------------------------------------
template<int K, int OTOT, int COLS, int KT, int NTH>
__device__ __forceinline__ void mm_pair2(const float* __restrict__ wfT, const float* __restrict__ wdT,
                                         const float* __restrict__ bufIn, float* smW,
                                         u64 accP[4][6], u64 accD[4][6],
                                         int o_base, int col_base, int tid)
{
    constexpr int TW    = KT * OTOT;
    constexpr int BUFSZ = 2 * TW;
    constexpr int NT    = K / KT;

    {
        const float4* sf = (const float4*)(wfT);
        const float4* sd = (const float4*)(wdT);
        for (int i = tid; i < TW / 4; i += NTH) {
            cpa16(smW + i * 4,        sf + i);
            cpa16(smW + TW + i * 4,   sd + i);
        }
        cp_commit();
    }
    for (int t = 0; t < NT; t++) {
        if (t + 1 < NT) {
            float* df = smW + ((t + 1) & 1) * BUFSZ;
            float* dd = df + TW;
            const float4* sf = (const float4*)(wfT + (t + 1) * KT * OTOT);
            const float4* sd = (const float4*)(wdT + (t + 1) * KT * OTOT);
            for (int i = tid; i < TW / 4; i += NTH) {
                cpa16(df + i * 4, sf + i);
                cpa16(dd + i * 4, sd + i);
            }
            cp_commit();
            cp_wait1();
        } else {
            cp_wait0();
        }
        __syncthreads();
        const float* Wf = smW + (t & 1) * BUFSZ;
        const float* Wd = Wf + TW;
#pragma unroll
        for (int kk = 0; kk < KT; kk++) {
            const ulonglong2* ar = (const ulonglong2*)(Wf + kk * OTOT + o_base);
            const ulonglong2* dr = (const ulonglong2*)(Wd + kk * OTOT + o_base);
            const float* br = bufIn + (t * KT + kk) * COLS + col_base;
            float2 b01 = *(const float2*)(br);
            float2 b23 = *(const float2*)(br + 2);
            float2 b45 = *(const float2*)(br + 4);
            u64 b2[6];
            b2[0] = packdup(b01.x); b2[1] = packdup(b01.y);
            b2[2] = packdup(b23.x); b2[3] = packdup(b23.y);
            b2[4] = packdup(b45.x); b2[5] = packdup(b45.y);
            ulonglong2 af0 = ar[0], af1 = ar[1], ad0 = dr[0], ad1 = dr[1];
            u64 a2f[4] = {af0.x, af0.y, af1.x, af1.y};
            u64 a2d[4] = {ad0.x, ad0.y, ad1.x, ad1.y};
#pragma unroll
            for (int op = 0; op < 4; op++)
#pragma unroll
                for (int cc = 0; cc < 6; cc++) {
                    ffma2(accP[op][cc], a2f[op], b2[cc]);
                    ffma2(accD[op][cc], a2d[op], b2[cc]);
                }
        }
        __syncthreads();
    }
}

template<int K, int OTOT, int COLS, int KT, int NTH>
__device__ __forceinline__ void mm_one2(const float* __restrict__ wT,
                                        const float* __restrict__ bufIn, float* smW,
                                        u64 acc[4][6], int o_base, int col_base, int tid)
{
    constexpr int TW  = KT * OTOT;
    constexpr int NT  = K / KT;

    {
        const float4* sf = (const float4*)(wT);
        for (int i = tid; i < TW / 4; i += NTH)
            cpa16(smW + i * 4, sf + i);
        cp_commit();
    }
    for (int t = 0; t < NT; t++) {
        if (t + 1 < NT) {
            float* df = smW + ((t + 1) & 1) * TW;
            const float4* sf = (const float4*)(wT + (t + 1) * KT * OTOT);
            for (int i = tid; i < TW / 4; i += NTH)
                cpa16(df + i * 4, sf + i);
            cp_commit();
            cp_wait1();
        } else {
            cp_wait0();
        }
        __syncthreads();
        const float* Wf = smW + (t & 1) * TW;
#pragma unroll
        for (int kk = 0; kk < KT; kk++) {
            const ulonglong2* ar = (const ulonglong2*)(Wf + kk * OTOT + o_base);
            const float* br = bufIn + (t * KT + kk) * COLS + col_base;
            float2 b01 = *(const float2*)(br);
            float2 b23 = *(const float2*)(br + 2);
            float2 b45 = *(const float2*)(br + 4);
            u64 b2[6];
            b2[0] = packdup(b01.x); b2[1] = packdup(b01.y);
            b2[2] = packdup(b23.x); b2[3] = packdup(b23.y);
            b2[4] = packdup(b45.x); b2[5] = packdup(b45.y);
            ulonglong2 af0 = ar[0], af1 = ar[1];
            u64 a2[4] = {af0.x, af0.y, af1.x, af1.y};
#pragma unroll
            for (int op = 0; op < 4; op++)
#pragma unroll
                for (int cc = 0; cc < 6; cc++)
                    ffma2(acc[op][cc], a2[op], b2[cc]);
        }
        __syncthreads();
    }
}

__device__ __forceinline__ void zero_acc(u64 a[4][6]) {
#pragma unroll
    for (int op = 0; op < 4; op++)
#pragma unroll
        for (int cc = 0; cc < 6; cc++) a[op][cc] = 0ull;
}

__device__ __forceinline__ void unpack_acc(const u64 a[4][6], float f[8][6]) {
#pragma unroll
    for (int op = 0; op < 4; op++)
#pragma unroll
        for (int cc = 0; cc < 6; cc++)
            unpack2(a[op][cc], f[2 * op][cc], f[2 * op + 1][cc]);
}

__device__ __forceinline__ void vn_combine(float accP[8][6], float accD[8][6])
{
#pragma unroll
    for (int oo = 0; oo < 8; oo++)
#pragma unroll
        for (int p = 0; p < 2; p++) {
            float p0 = accP[oo][3 * p], p1 = accP[oo][3 * p + 1], p2 = accP[oo][3 * p + 2];
            float q0 = accD[oo][3 * p], q1 = accD[oo][3 * p + 1], q2 = accD[oo][3 * p + 2];
            float dot = p0 * q0 + p1 * q1 + p2 * q2;
            float dn  = q0 * q0 + q1 * q1 + q2 * q2;
            if (dot < 0.f) {
                float s = dot / (dn + EPSV);
                accP[oo][3 * p]     = p0 - s * q0;
                accP[oo][3 * p + 1] = p1 - s * q1;
                accP[oo][3 * p + 2] = p2 - s * q2;
            }
        }
}

template<int COLS>
__device__ __forceinline__ void store_tile(float* buf, float acc[8][6], int o_base, int col_base)
{
#pragma unroll
    for (int oo = 0; oo < 8; oo++) {
        float* r = buf + (o_base + oo) * COLS + col_base;
#pragma unroll
        for (int cc = 0; cc < 6; cc++) r[cc] = acc[oo][cc];
    }
}

// ---------------------------------------------------------------------------
// setup kernels
// ---------------------------------------------------------------------------
__global__ void k_initkeys()
{
    int i = blockIdx.x * blockDim.x + threadIdx.x;
    if (i < NSEG * 128) d_key1[i] = 0ull;
    if (i < NSEG * 256) d_key2[i] = 0ull;
}

struct TList {
    const float* src[7];
    int off[7];
};

__global__ void k_tmany(TList tl, int O, int C)
{
    __shared__ float t[32][33];
    const float* src = tl.src[blockIdx.z];
    int dstOff = tl.off[blockIdx.z];
    int cb = blockIdx.x * 32, ob = blockIdx.y * 32;
    int x = threadIdx.x, y = threadIdx.y;
    for (int i = y; i < 32; i += 8) t[i][x] = src[(size_t)(ob + i) * C + cb + x];
    __syncthreads();
    for (int i = y; i < 32; i += 8) d_wt[dstOff + (size_t)(cb + i) * O + ob + x] = t[x][i];
}

// ---------------------------------------------------------------------------
// stage 1: 48 points per CTA, 384 threads (16 o-groups x 24 col-groups)
// smem: bufA [128][144] (72KB) + smW 64KB = 136KB dynamic; sk 2KB static
// Last CTA: points >= NPTS are clamped on load, masked on store/argmax.
// CTA may span one segment boundary -> 2-slot smem key table.
// ---------------------------------------------------------------------------
__global__ void __launch_bounds__(384, 1) k_stage1(const float* __restrict__ x,
                                                   const int* __restrict__ radius)
{
    extern __shared__ float sm[];
    float* bufA = sm;                  // [128][144]
    float* smW  = sm + 18432;          // 4 x [32][128]
    __shared__ u64 sk[2 * 128];
    int tid = threadIdx.x;
    int n0 = blockIdx.x * 48;

    for (int i = tid; i < 256; i += 384) sk[i] = 0ull;

    // load X tile transposed (point-clamped): bufA[c][p*3+j] = x[n_eff][c][j]
    for (int i4 = tid; i4 < 4608; i4 += 384) {
        int p = i4 / 96;                       // local point 0..47
        int n = n0 + p; if (n >= NPTS) n = NPTS - 1;
        int q = i4 - p * 96;                   // float4 within point
        float4 v = ((const float4*)x)[(size_t)n * 96 + q];
        int r = q * 4;
        float vv[4] = {v.x, v.y, v.z, v.w};
#pragma unroll
        for (int e = 0; e < 4; e++) {
            int rr = r + e;
            int c = rr / 3, j = rr - c * 3;
            bufA[c * 144 + p * 3 + j] = vv[e];
        }
    }

    int ty = tid / 24, tx = tid % 24;
    int o_base = ty * 8, col_base = tx * 6;

    u64 aP[4][6], aD[4][6];
    float fP[8][6], fD[8][6];

    zero_acc(aP); zero_acc(aD);
    mm_pair2<128, 128, 144, 32, 384>(d_wt + O_W1F, d_wt + O_W1D, bufA, smW, aP, aD, o_base, col_base, tid);
    unpack_acc(aP, fP); unpack_acc(aD, fD);
    vn_combine(fP, fD);
    store_tile<144>(bufA, fP, o_base, col_base);

    zero_acc(aP); zero_acc(aD);
    mm_pair2<128, 128, 144, 32, 384>(d_wt + O_W2F, d_wt + O_W2D, bufA, smW, aP, aD, o_base, col_base, tid);
    unpack_acc(aP, fP); unpack_acc(aD, fD);
    vn_combine(fP, fD);
    store_tile<144>(bufA, fP, o_base, col_base);

    zero_acc(aP);
    mm_one2<128, 128, 144, 32, 384>(d_wt + O_W3, bufA, smW, aP, o_base, col_base, tid);
    unpack_acc(aP, fP);
    store_tile<144>(bufA, fP, o_base, col_base);

    // write g3 (guard per point)
    int nA0 = n0 + 2 * tx, nA1 = nA0 + 1;
    bool v0 = nA0 < NPTS, v1 = nA1 < NPTS;
#pragma unroll
    for (int oo = 0; oo < 8; oo++) {
        float* g = d_g3s + (size_t)(o_base + oo) * NT3;
        if (v0) { g[(size_t)nA0*3] = fP[oo][0]; g[(size_t)nA0*3+1] = fP[oo][1]; g[(size_t)nA0*3+2] = fP[oo][2]; }
        if (v1) { g[(size_t)nA1*3] = fP[oo][3]; g[(size_t)nA1*3+1] = fP[oo][4]; g[(size_t)nA1*3+2] = fP[oo][5]; }
    }

    zero_acc(aD);
    mm_one2<128, 128, 144, 32, 384>(d_wt + O_WD1, bufA, smW, aD, o_base, col_base, tid);
    unpack_acc(aD, fD);

    // argmax via smem key table (2 segment slots)
    int seg0 = radius[n0];
    int si0 = v0 ? (radius[nA0] != seg0 ? 1 : 0) : 0;
    int si1 = v1 ? (radius[nA1] != seg0 ? 1 : 0) : 0;
#pragma unroll
    for (int oo = 0; oo < 8; oo++) {
        if (v0) {
            float dot0 = fP[oo][0]*fD[oo][0] + fP[oo][1]*fD[oo][1] + fP[oo][2]*fD[oo][2];
            atomicMax(&sk[si0 * 128 + o_base + oo], packkey(dot0, (unsigned)nA0));
        }
        if (v1) {
            float dot1 = fP[oo][3]*fD[oo][3] + fP[oo][4]*fD[oo][4] + fP[oo][5]*fD[oo][5];
            atomicMax(&sk[si1 * 128 + o_base + oo], packkey(dot1, (unsigned)nA1));
        }
    }
    __syncthreads();
    for (int i = tid; i < 256; i += 384) {
        u64 v = sk[i];
        if (v) atomicMax(&d_key1[(seg0 + (i >> 7)) * 128 + (i & 127)], v);
    }
}

// ---------------------------------------------------------------------------
// gather + relu3
// ---------------------------------------------------------------------------
__global__ void k_relu3()
{
    __shared__ float G[128][3];
    int seg = blockIdx.x, c = threadIdx.x;
    u64 key = d_key1[seg * 128 + c];
    unsigned int idx = 0xFFFFFFFFu - (unsigned int)(key & 0xFFFFFFFFull);
    if (idx >= NPTS) idx = 0;
    float g0 = d_g3s[(size_t)c * NT3 + (size_t)idx * 3 + 0];
    float g1 = d_g3s[(size_t)c * NT3 + (size_t)idx * 3 + 1];
    float g2 = d_g3s[(size_t)c * NT3 + (size_t)idx * 3 + 2];
    G[c][0] = g0; G[c][1] = g1; G[c][2] = g2;
    __syncthreads();
    float a0 = 0.f, a1 = 0.f, a2 = 0.f;
    const float* w = d_wt + O_WR3;
    for (int k = 0; k < 128; k++) {
        float ww = w[k * 128 + c];
        a0 += ww * G[k][0]; a1 += ww * G[k][1]; a2 += ww * G[k][2];
    }
    float dot = g0 * a0 + g1 * a1 + g2 * a2;
    float dn  = a0 * a0 + a1 * a1 + a2 * a2;
    float o0 = g0, o1 = g1, o2 = g2;
    if (dot < 0.f) {
        float s = dot / (dn + EPSV);
        o0 -= s * a0; o1 -= s * a1; o2 -= s * a2;
    }
    d_r3[seg * 384 + c * 3 + 0] = o0;
    d_r3[seg * 384 + c * 3 + 1] = o1;
    d_r3[seg * 384 + c * 3 + 2] = o2;
}

// ---------------------------------------------------------------------------
// stage 2: 24 points per CTA, 384 threads (32 o-groups x 12 col-groups)
// smem: bufA [256][72] (72KB) + smW 128KB = 200KB dynamic; sk 4KB static
// ---------------------------------------------------------------------------
__global__ void __launch_bounds__(384, 1) k_stage2(const float* __restrict__ x,
                                                   const int* __restrict__ radius)
{
    extern __shared__ float sm[];
    float* bufA = sm;                  // [256][72]
    float* smW  = sm + 18432;          // 4 x [32][256]
    __shared__ u64 sk[2 * 256];
    int tid = threadIdx.x;
    int n0 = blockIdx.x * 24;

    for (int i = tid; i < 512; i += 384) sk[i] = 0ull;

    // x part (clamped): bufA[c][p*3+j], c < 128
    for (int i4 = tid; i4 < 2304; i4 += 384) {
        int p = i4 / 96;
        int n = n0 + p; if (n >= NPTS) n = NPTS - 1;
        int q = i4 - p * 96;
        float4 v = ((const float4*)x)[(size_t)n * 96 + q];
        int r = q * 4;
        float vv[4] = {v.x, v.y, v.z, v.w};
#pragma unroll
        for (int e = 0; e < 4; e++) {
            int rr = r + e;
            int c = rr / 3, j = rr - c * 3;
            bufA[c * 72 + p * 3 + j] = vv[e];
        }
    }
    // r3 broadcast part (per-point segment): bufA[128+c][p*3+j] = r3[radius[n]][c][j]
    for (int i = tid; i < 128 * 72; i += 384) {
        int c = i / 72, col = i - c * 72;
        int p = col / 3, j = col - p * 3;
        int n = n0 + p; if (n >= NPTS) n = NPTS - 1;
        int seg = radius[n];
        bufA[(128 + c) * 72 + col] = d_r3[seg * 384 + c * 3 + j];
    }

    int ty = tid / 12, tx = tid % 12;
    int o_base = ty * 8, col_base = tx * 6;

    u64 aP[4][6], aD[4][6];
    float fP[8][6], fD[8][6];

    zero_acc(aP); zero_acc(aD);
    mm_pair2<256, 256, 72, 32, 384>(d_wt + O_W4F, d_wt + O_W4D, bufA, smW, aP, aD, o_base, col_base, tid);
    unpack_acc(aP, fP); unpack_acc(aD, fD);
    vn_combine(fP, fD);
    store_tile<72>(bufA, fP, o_base, col_base);

    zero_acc(aP);
    mm_one2<256, 256, 72, 32, 384>(d_wt + O_W5, bufA, smW, aP, o_base, col_base, tid);
    unpack_acc(aP, fP);
    store_tile<72>(bufA, fP, o_base, col_base);

    int nA0 = n0 + 2 * tx, nA1 = nA0 + 1;
    bool v0 = nA0 < NPTS, v1 = nA1 < NPTS;
#pragma unroll
    for (int oo = 0; oo < 8; oo++) {
        float* g = d_h5s + (size_t)(o_base + oo) * NT3;
        if (v0) { g[(size_t)nA0*3] = fP[oo][0]; g[(size_t)nA0*3+1] = fP[oo][1]; g[(size_t)nA0*3+2] = fP[oo][2]; }
        if (v1) { g[(size_t)nA1*3] = fP[oo][3]; g[(size_t)nA1*3+1] = fP[oo][4]; g[(size_t)nA1*3+2] = fP[oo][5]; }
    }

    zero_acc(aD);
    mm_one2<256, 256, 72, 32, 384>(d_wt + O_WD2, bufA, smW, aD, o_base, col_base, tid);
    unpack_acc(aD, fD);

    int seg0 = radius[n0];
    int si0 = v0 ? (radius[nA0] != seg0 ? 1 : 0) : 0;
    int si1 = v1 ? (radius[nA1] != seg0 ? 1 : 0) : 0;
#pragma unroll
    for (int oo = 0; oo < 8; oo++) {
        if (v0) {
            float dot0 = fP[oo][0]*fD[oo][0] + fP[oo][1]*fD[oo][1] + fP[oo][2]*fD[oo][2];
            atomicMax(&sk[si0 * 256 + o_base + oo], packkey(dot0, (unsigned)nA0));
        }
        if (v1) {
            float dot1 = fP[oo][3]*fD[oo][3] + fP[oo][4]*fD[oo][4] + fP[oo][5]*fD[oo][5];
            atomicMax(&sk[si1 * 256 + o_base + oo], packkey(dot1, (unsigned)nA1));
        }
    }
    __syncthreads();
    for (int i = tid; i < 512; i += 384) {
        u64 v = sk[i];
        if (v) atomicMax(&d_key2[(seg0 + (i >> 8)) * 256 + (i & 255)], v);
    }
}

// ---------------------------------------------------------------------------
// gather + relu5 -> output
// ---------------------------------------------------------------------------
__global__ void k_relu5(float* __restrict__ out)
{
    __shared__ float G[256][3];
    int seg = blockIdx.x, c = threadIdx.x;
    u64 key = d_key2[seg * 256 + c];
    unsigned int idx = 0xFFFFFFFFu - (unsigned int)(key & 0xFFFFFFFFull);
    if (idx >= NPTS) idx = 0;
    float g0 = d_h5s[(size_t)c * NT3 + (size_t)idx * 3 + 0];
    float g1 = d_h5s[(size_t)c * NT3 + (size_t)idx * 3 + 1];
    float g2 = d_h5s[(size_t)c * NT3 + (size_t)idx * 3 + 2];
    G[c][0] = g0; G[c][1] = g1; G[c][2] = g2;
    __syncthreads();
    float a0 = 0.f, a1 = 0.f, a2 = 0.f;
    const float* w = d_wt + O_WR5;
    for (int k = 0; k < 256; k++) {
        float ww = w[k * 256 + c];
        a0 += ww * G[k][0]; a1 += ww * G[k][1]; a2 += ww * G[k][2];
    }
    float dot = g0 * a0 + g1 * a1 + g2 * a2;
    float dn  = a0 * a0 + a1 * a1 + a2 * a2;
    float o0 = g0, o1 = g1, o2 = g2;
    if (dot < 0.f) {
        float s = dot / (dn + EPSV);
        o0 -= s * a0; o1 -= s * a1; o2 -= s * a2;
    }
    out[seg * 768 + c * 3 + 0] = o0;
    out[seg * 768 + c * 3 + 1] = o1;
    out[seg * 768 + c * 3 + 2] = o2;
}

// ---------------------------------------------------------------------------
// host launcher
// ---------------------------------------------------------------------------
extern "C" void kernel_launch(void* const* d_in, const int* in_sizes, int n_in,
                              void* d_out, int out_size)
{
    const float* x      = (const float*)d_in[0];
    const int*   radius = (const int*)d_in[1];

    cudaFuncSetAttribute(k_stage1, cudaFuncAttributeMaxDynamicSharedMemorySize, 139264);
    cudaFuncSetAttribute(k_stage2, cudaFuncAttributeMaxDynamicSharedMemorySize, 204800);

    k_initkeys<<<32, 256>>>();

    dim3 tb(32, 8);
    TList t128;
    t128.src[0] = (const float*)d_in[2];  t128.off[0] = O_W1F;
    t128.src[1] = (const float*)d_in[3];  t128.off[1] = O_W1D;
    t128.src[2] = (const float*)d_in[4];  t128.off[2] = O_W2F;
    t128.src[3] = (const float*)d_in[5];  t128.off[3] = O_W2D;
    t128.src[4] = (const float*)d_in[6];  t128.off[4] = O_W3;
    t128.src[5] = (const float*)d_in[7];  t128.off[5] = O_WD1;
    t128.src[6] = (const float*)d_in[8];  t128.off[6] = O_WR3;
    k_tmany<<<dim3(4, 4, 7), tb>>>(t128, 128, 128);

    TList t256;
    t256.src[0] = (const float*)d_in[9];   t256.off[0] = O_W4F;
    t256.src[1] = (const float*)d_in[10];  t256.off[1] = O_W4D;
    t256.src[2] = (const float*)d_in[11];  t256.off[2] = O_W5;
    t256.src[3] = (const float*)d_in[12];  t256.off[3] = O_WD2;
    t256.src[4] = (const float*)d_in[13];  t256.off[4] = O_WR5;
    t256.src[5] = t256.src[4];             t256.off[5] = O_WR5;  // unused (grid.z=5)
    t256.src[6] = t256.src[4];             t256.off[6] = O_WR5;
    k_tmany<<<dim3(8, 8, 5), tb>>>(t256, 256, 256);

    k_stage1<<<(NPTS + 47) / 48, 384, 139264>>>(x, radius);
    k_relu3<<<NSEG, 128>>>();
    k_stage2<<<(NPTS + 23) / 24, 384, 204800>>>(x, radius);
    k_relu5<<<NSEG, 256>>>((float*)d_out);
}

// round 12
// speedup vs baseline: 1.3323x; 1.1444x over previous
#include <cuda_runtime.h>

#define EPSV 1e-7f
#define NPTS 131072
#define NT3  393216
#define NSEG 32

#define O_W1F 0
#define O_W1D 16384
#define O_W2F 32768
#define O_W2D 49152
#define O_W3  65536
#define O_WD1 81920
#define O_WR3 98304
#define O_W4F 114688
#define O_W4D 180224
#define O_W5  245760
#define O_WD2 311296
#define O_WR5 376832
#define WT_TOTAL 442368

__device__ float d_wt[WT_TOTAL];
__device__ float d_g3s[128ull * (unsigned long long)NT3];
__device__ float d_h5s[256ull * (unsigned long long)NT3];
__device__ float d_r3[NSEG * 128 * 3];
__device__ float d_c4f[NSEG * 256 * 3];   // per-seg constant: W4f[:,128:] @ r3[seg]
__device__ float d_c4d[NSEG * 256 * 3];
__device__ unsigned long long d_key1[NSEG * 128];
__device__ unsigned long long d_key2[NSEG * 256];

typedef unsigned long long u64;

__device__ __forceinline__ u64 packkey(float dot, unsigned int n) {
    unsigned int u = __float_as_uint(dot);
    u = (u & 0x80000000u) ? ~u : (u | 0x80000000u);
    return ((u64)u << 32) | (u64)(0xFFFFFFFFu - n);
}

__device__ __forceinline__ void ffma2(u64& d, u64 a, u64 b) {
    asm("fma.rn.f32x2 %0, %1, %2, %0;" : "+l"(d) : "l"(a), "l"(b));
}
__device__ __forceinline__ u64 packdup(float x) {
    u64 r;
    asm("mov.b64 %0, {%1, %1};" : "=l"(r) : "r"(__float_as_uint(x)));
    return r;
}
__device__ __forceinline__ void unpack2(u64 v, float& lo, float& hi) {
    unsigned int l, h;
    asm("mov.b64 {%0, %1}, %2;" : "=r"(l), "=r"(h) : "l"(v));
    lo = __uint_as_float(l);
    hi = __uint_as_float(h);
}

__device__ __forceinline__ void cpa16(float* smdst, const float4* gsrc) {
    unsigned s = (unsigned)__cvta_generic_to_shared(smdst);
    asm volatile("cp.async.cg.shared.global [%0], [%1], 16;" :: "r"(s), "l"(gsrc));
}
__device__ __forceinline__ void cp_commit() { asm volatile("cp.async.commit_group;"); }
__device__ __forceinline__ void cp_wait1() { asm volatile("cp.async.wait_group 1;" ::: "memory"); }
__device__ __forceinline__ void cp_wait0() { asm volatile("cp.async.wait_group 0;" ::: "memory"); }

// ---------------------------------------------------------------------------
// matmul cores (R11-proven). Thread tile 8 channels (4 packed pairs) x 6 cols.
// ---------------------------------------------------------------------------
template<int K, int OTOT, int COLS, int KT, int NTH>
__device__ __forceinline__ void mm_pair2(const float* __restrict__ wfT, const float* __restrict__ wdT,
                                         const float* __restrict__ bufIn, float* smW,
                                         u64 accP[4][6], u64 accD[4][6],
                                         int o_base, int col_base, int tid)
{
    constexpr int TW    = KT * OTOT;
    constexpr int BUFSZ = 2 * TW;
    constexpr int NT    = K / KT;

    {
        const float4* sf = (const float4*)(wfT);
        const float4* sd = (const float4*)(wdT);
        for (int i = tid; i < TW / 4; i += NTH) {
            cpa16(smW + i * 4,        sf + i);
            cpa16(smW + TW + i * 4,   sd + i);
        }
        cp_commit();
    }
    for (int t = 0; t < NT; t++) {
        if (t + 1 < NT) {
            float* df = smW + ((t + 1) & 1) * BUFSZ;
            float* dd = df + TW;
            const float4* sf = (const float4*)(wfT + (t + 1) * KT * OTOT);
            const float4* sd = (const float4*)(wdT + (t + 1) * KT * OTOT);
            for (int i = tid; i < TW / 4; i += NTH) {
                cpa16(df + i * 4, sf + i);
                cpa16(dd + i * 4, sd + i);
            }
            cp_commit();
            cp_wait1();
        } else {
            cp_wait0();
        }
        __syncthreads();
        const float* Wf = smW + (t & 1) * BUFSZ;
        const float* Wd = Wf + TW;
#pragma unroll
        for (int kk = 0; kk < KT; kk++) {
            const ulonglong2* ar = (const ulonglong2*)(Wf + kk * OTOT + o_base);
            const ulonglong2* dr = (const ulonglong2*)(Wd + kk * OTOT + o_base);
            const float* br = bufIn + (t * KT + kk) * COLS + col_base;
            float2 b01 = *(const float2*)(br);
            float2 b23 = *(const float2*)(br + 2);
            float2 b45 = *(const float2*)(br + 4);
            u64 b2[6];
            b2[0] = packdup(b01.x); b2[1] = packdup(b01.y);
            b2[2] = packdup(b23.x); b2[3] = packdup(b23.y);
            b2[4] = packdup(b45.x); b2[5] = packdup(b45.y);
            ulonglong2 af0 = ar[0], af1 = ar[1], ad0 = dr[0], ad1 = dr[1];
            u64 a2f[4] = {af0.x, af0.y, af1.x, af1.y};
            u64 a2d[4] = {ad0.x, ad0.y, ad1.x, ad1.y};
#pragma unroll
            for (int op = 0; op < 4; op++)
#pragma unroll
                for (int cc = 0; cc < 6; cc++) {
                    ffma2(accP[op][cc], a2f[op], b2[cc]);
                    ffma2(accD[op][cc], a2d[op], b2[cc]);
                }
        }
        __syncthreads();
    }
}

template<int K, int OTOT, int COLS, int KT, int NTH>
__device__ __forceinline__ void mm_one2(const float* __restrict__ wT,
                                        const float* __restrict__ bufIn, float* smW,
                                        u64 acc[4][6], int o_base, int col_base, int tid)
{
    constexpr int TW  = KT * OTOT;
    constexpr int NT  = K / KT;

    {
        const float4* sf = (const float4*)(wT);
        for (int i = tid; i < TW / 4; i += NTH)
            cpa16(smW + i * 4, sf + i);
        cp_commit();
    }
    for (int t = 0; t < NT; t++) {
        if (t + 1 < NT) {
            float* df = smW + ((t + 1) & 1) * TW;
            const float4* sf = (const float4*)(wT + (t + 1) * KT * OTOT);
            for (int i = tid; i < TW / 4; i += NTH)
                cpa16(df + i * 4, sf + i);
            cp_commit();
            cp_wait1();
        } else {
            cp_wait0();
        }
        __syncthreads();
        const float* Wf = smW + (t & 1) * TW;
#pragma unroll
        for (int kk = 0; kk < KT; kk++) {
            const ulonglong2* ar = (const ulonglong2*)(Wf + kk * OTOT + o_base);
            const float* br = bufIn + (t * KT + kk) * COLS + col_base;
            float2 b01 = *(const float2*)(br);
            float2 b23 = *(const float2*)(br + 2);
            float2 b45 = *(const float2*)(br + 4);
            u64 b2[6];
            b2[0] = packdup(b01.x); b2[1] = packdup(b01.y);
            b2[2] = packdup(b23.x); b2[3] = packdup(b23.y);
            b2[4] = packdup(b45.x); b2[5] = packdup(b45.y);
            ulonglong2 af0 = ar[0], af1 = ar[1];
            u64 a2[4] = {af0.x, af0.y, af1.x, af1.y};
#pragma unroll
            for (int op = 0; op < 4; op++)
#pragma unroll
                for (int cc = 0; cc < 6; cc++)
                    ffma2(acc[op][cc], a2[op], b2[cc]);
        }
        __syncthreads();
    }
}

__device__ __forceinline__ void zero_acc(u64 a[4][6]) {
#pragma unroll
    for (int op = 0; op < 4; op++)
#pragma unroll
        for (int cc = 0; cc < 6; cc++) a[op][cc] = 0ull;
}

__device__ __forceinline__ void unpack_acc(const u64 a[4][6], float f[8][6]) {
#pragma unroll
    for (int op = 0; op < 4; op++)
#pragma unroll
        for (int cc = 0; cc < 6; cc++)
            unpack2(a[op][cc], f[2 * op][cc], f[2 * op + 1][cc]);
}

__device__ __forceinline__ void vn_combine(float accP[8][6], float accD[8][6])
{
#pragma unroll
    for (int oo = 0; oo < 8; oo++)
#pragma unroll
        for (int p = 0; p < 2; p++) {
            float p0 = accP[oo][3 * p], p1 = accP[oo][3 * p + 1], p2 = accP[oo][3 * p + 2];
            float q0 = accD[oo][3 * p], q1 = accD[oo][3 * p + 1], q2 = accD[oo][3 * p + 2];
            float dot = p0 * q0 + p1 * q1 + p2 * q2;
            float dn  = q0 * q0 + q1 * q1 + q2 * q2;
            if (dot < 0.f) {
                float s = dot / (dn + EPSV);
                accP[oo][3 * p]     = p0 - s * q0;
                accP[oo][3 * p + 1] = p1 - s * q1;
                accP[oo][3 * p + 2] = p2 - s * q2;
            }
        }
}

template<int COLS>
__device__ __forceinline__ void store_tile(float* buf, float acc[8][6], int o_base, int col_base)
{
#pragma unroll
    for (int oo = 0; oo < 8; oo++) {
        float* r = buf + (o_base + oo) * COLS + col_base;
#pragma unroll
        for (int cc = 0; cc < 6; cc++) r[cc] = acc[oo][cc];
    }
}

// ---------------------------------------------------------------------------
// setup kernels
// ---------------------------------------------------------------------------
__global__ void k_initkeys()
{
    int i = blockIdx.x * blockDim.x + threadIdx.x;
    if (i < NSEG * 128) d_key1[i] = 0ull;
    if (i < NSEG * 256) d_key2[i] = 0ull;
}

struct TList {
    const float* src[7];
    int off[7];
};

__global__ void k_tmany(TList tl, int O, int C)
{
    __shared__ float t[32][33];
    const float* src = tl.src[blockIdx.z];
    int dstOff = tl.off[blockIdx.z];
    int cb = blockIdx.x * 32, ob = blockIdx.y * 32;
    int x = threadIdx.x, y = threadIdx.y;
    for (int i = y; i < 32; i += 8) t[i][x] = src[(size_t)(ob + i) * C + cb + x];
    __syncthreads();
    for (int i = y; i < 32; i += 8) d_wt[dstOff + (size_t)(cb + i) * O + ob + x] = t[x][i];
}

// per-segment vn4 constants: C4{f,d}[seg][o][j] = sum_{c<128} W4{f,d}[o][128+c] * r3[seg][c][j]
__global__ void k_c4(const float* __restrict__ W4f, const float* __restrict__ W4d)
{
    int seg = blockIdx.x, o = threadIdx.x;
    const float* r3s = d_r3 + seg * 384;
    float f0 = 0.f, f1 = 0.f, f2 = 0.f, e0 = 0.f, e1 = 0.f, e2 = 0.f;
    for (int c = 0; c < 128; c++) {
        float wf = W4f[(size_t)o * 256 + 128 + c];
        float wd = W4d[(size_t)o * 256 + 128 + c];
        float g0 = r3s[c * 3], g1 = r3s[c * 3 + 1], g2 = r3s[c * 3 + 2];
        f0 += wf * g0; f1 += wf * g1; f2 += wf * g2;
        e0 += wd * g0; e1 += wd * g1; e2 += wd * g2;
    }
    d_c4f[seg * 768 + o * 3 + 0] = f0;
    d_c4f[seg * 768 + o * 3 + 1] = f1;
    d_c4f[seg * 768 + o * 3 + 2] = f2;
    d_c4d[seg * 768 + o * 3 + 0] = e0;
    d_c4d[seg * 768 + o * 3 + 1] = e1;
    d_c4d[seg * 768 + o * 3 + 2] = e2;
}

// ---------------------------------------------------------------------------
// stage 1 (unchanged from R11): 48 points per CTA, 384 threads
// ---------------------------------------------------------------------------
__global__ void __launch_bounds__(384, 1) k_stage1(const float* __restrict__ x,
                                                   const int* __restrict__ radius)
{
    extern __shared__ float sm[];
    float* bufA = sm;                  // [128][144]
    float* smW  = sm + 18432;
    __shared__ u64 sk[2 * 128];
    int tid = threadIdx.x;
    int n0 = blockIdx.x * 48;

    for (int i = tid; i < 256; i += 384) sk[i] = 0ull;

    for (int i4 = tid; i4 < 4608; i4 += 384) {
        int p = i4 / 96;
        int n = n0 + p; if (n >= NPTS) n = NPTS - 1;
        int q = i4 - p * 96;
        float4 v = ((const float4*)x)[(size_t)n * 96 + q];
        int r = q * 4;
        float vv[4] = {v.x, v.y, v.z, v.w};
#pragma unroll
        for (int e = 0; e < 4; e++) {
            int rr = r + e;
            int c = rr / 3, j = rr - c * 3;
            bufA[c * 144 + p * 3 + j] = vv[e];
        }
    }

    int ty = tid / 24, tx = tid % 24;
    int o_base = ty * 8, col_base = tx * 6;

    u64 aP[4][6], aD[4][6];
    float fP[8][6], fD[8][6];

    zero_acc(aP); zero_acc(aD);
    mm_pair2<128, 128, 144, 32, 384>(d_wt + O_W1F, d_wt + O_W1D, bufA, smW, aP, aD, o_base, col_base, tid);
    unpack_acc(aP, fP); unpack_acc(aD, fD);
    vn_combine(fP, fD);
    store_tile<144>(bufA, fP, o_base, col_base);

    zero_acc(aP); zero_acc(aD);
    mm_pair2<128, 128, 144, 32, 384>(d_wt + O_W2F, d_wt + O_W2D, bufA, smW, aP, aD, o_base, col_base, tid);
    unpack_acc(aP, fP); unpack_acc(aD, fD);
    vn_combine(fP, fD);
    store_tile<144>(bufA, fP, o_base, col_base);

    zero_acc(aP);
    mm_one2<128, 128, 144, 32, 384>(d_wt + O_W3, bufA, smW, aP, o_base, col_base, tid);
    unpack_acc(aP, fP);
    store_tile<144>(bufA, fP, o_base, col_base);

    int nA0 = n0 + 2 * tx, nA1 = nA0 + 1;
    bool v0 = nA0 < NPTS, v1 = nA1 < NPTS;
#pragma unroll
    for (int oo = 0; oo < 8; oo++) {
        float* g = d_g3s + (size_t)(o_base + oo) * NT3;
        if (v0) { g[(size_t)nA0*3] = fP[oo][0]; g[(size_t)nA0*3+1] = fP[oo][1]; g[(size_t)nA0*3+2] = fP[oo][2]; }
        if (v1) { g[(size_t)nA1*3] = fP[oo][3]; g[(size_t)nA1*3+1] = fP[oo][4]; g[(size_t)nA1*3+2] = fP[oo][5]; }
    }

    zero_acc(aD);
    mm_one2<128, 128, 144, 32, 384>(d_wt + O_WD1, bufA, smW, aD, o_base, col_base, tid);
    unpack_acc(aD, fD);

    int seg0 = radius[n0];
    int si0 = v0 ? (radius[nA0] != seg0 ? 1 : 0) : 0;
    int si1 = v1 ? (radius[nA1] != seg0 ? 1 : 0) : 0;
#pragma unroll
    for (int oo = 0; oo < 8; oo++) {
        if (v0) {
            float dot0 = fP[oo][0]*fD[oo][0] + fP[oo][1]*fD[oo][1] + fP[oo][2]*fD[oo][2];
            atomicMax(&sk[si0 * 128 + o_base + oo], packkey(dot0, (unsigned)nA0));
        }
        if (v1) {
            float dot1 = fP[oo][3]*fD[oo][3] + fP[oo][4]*fD[oo][4] + fP[oo][5]*fD[oo][5];
            atomicMax(&sk[si1 * 128 + o_base + oo], packkey(dot1, (unsigned)nA1));
        }
    }
    __syncthreads();
    for (int i = tid; i < 256; i += 384) {
        u64 v = sk[i];
        if (v) atomicMax(&d_key1[(seg0 + (i >> 7)) * 128 + (i & 127)], v);
    }
}

// ---------------------------------------------------------------------------
// gather + relu3
// ---------------------------------------------------------------------------
__global__ void k_relu3()
{
    __shared__ float G[128][3];
    int seg = blockIdx.x, c = threadIdx.x;
    u64 key = d_key1[seg * 128 + c];
    unsigned int idx = 0xFFFFFFFFu - (unsigned int)(key & 0xFFFFFFFFull);
    if (idx >= NPTS) idx = 0;
    float g0 = d_g3s[(size_t)c * NT3 + (size_t)idx * 3 + 0];
    float g1 = d_g3s[(size_t)c * NT3 + (size_t)idx * 3 + 1];
    float g2 = d_g3s[(size_t)c * NT3 + (size_t)idx * 3 + 2];
    G[c][0] = g0; G[c][1] = g1; G[c][2] = g2;
    __syncthreads();
    float a0 = 0.f, a1 = 0.f, a2 = 0.f;
    const float* w = d_wt + O_WR3;
    for (int k = 0; k < 128; k++) {
        float ww = w[k * 128 + c];
        a0 += ww * G[k][0]; a1 += ww * G[k][1]; a2 += ww * G[k][2];
    }
    float dot = g0 * a0 + g1 * a1 + g2 * a2;
    float dn  = a0 * a0 + a1 * a1 + a2 * a2;
    float o0 = g0, o1 = g1, o2 = g2;
    if (dot < 0.f) {
        float s = dot / (dn + EPSV);
        o0 -= s * a0; o1 -= s * a1; o2 -= s * a2;
    }
    d_r3[seg * 384 + c * 3 + 0] = o0;
    d_r3[seg * 384 + c * 3 + 1] = o1;
    d_r3[seg * 384 + c * 3 + 2] = o2;
}

// ---------------------------------------------------------------------------
// stage 2: vn4 split into x-part matmul (K=128) + per-seg constant C4.
// 24 points per CTA, 384 threads. Single buf [256][72]: x in rows 0..127,
// overwritten by vn4 output (all mm reads complete before stores).
// smem: buf 72KB + smW 128KB = 200KB dyn; sk 4KB + sc4 12KB static.
// ---------------------------------------------------------------------------
__global__ void __launch_bounds__(384, 1) k_stage2(const float* __restrict__ x,
                                                   const int* __restrict__ radius)
{
    extern __shared__ float sm[];
    float* bufA = sm;                  // [256][72]
    float* smW  = sm + 18432;
    __shared__ u64 sk[2 * 256];
    __shared__ float scf[2][768];      // C4f for slot 0/1 segments
    __shared__ float scd[2][768];
    int tid = threadIdx.x;
    int n0 = blockIdx.x * 24;

    for (int i = tid; i < 512; i += 384) sk[i] = 0ull;

    int seg0 = radius[n0];
    int seg1 = seg0 + 1; if (seg1 >= NSEG) seg1 = NSEG - 1;
    for (int i = tid; i < 2 * 768; i += 384) {
        int slot = i / 768, r = i - slot * 768;
        int sg = slot ? seg1 : seg0;
        scf[slot][r] = d_c4f[sg * 768 + r];
        scd[slot][r] = d_c4d[sg * 768 + r];
    }

    // x part (clamped): bufA[c][p*3+j], c < 128
    for (int i4 = tid; i4 < 2304; i4 += 384) {
        int p = i4 / 96;
        int n = n0 + p; if (n >= NPTS) n = NPTS - 1;
        int q = i4 - p * 96;
        float4 v = ((const float4*)x)[(size_t)n * 96 + q];
        int r = q * 4;
        float vv[4] = {v.x, v.y, v.z, v.w};
#pragma unroll
        for (int e = 0; e < 4; e++) {
            int rr = r + e;
            int c = rr / 3, j = rr - c * 3;
            bufA[c * 72 + p * 3 + j] = vv[e];
        }
    }

    int ty = tid / 12, tx = tid % 12;
    int o_base = ty * 8, col_base = tx * 6;

    int nA0 = n0 + 2 * tx, nA1 = nA0 + 1;
    bool v0 = nA0 < NPTS, v1 = nA1 < NPTS;
    int si0 = v0 ? (radius[nA0] != seg0 ? 1 : 0) : 0;
    int si1 = v1 ? (radius[nA1] != seg0 ? 1 : 0) : 0;

    u64 aP[4][6], aD[4][6];
    float fP[8][6], fD[8][6];

    // L4: vn4 = W4[:, :128] @ x  + C4[seg]
    zero_acc(aP); zero_acc(aD);
    mm_pair2<128, 256, 72, 32, 384>(d_wt + O_W4F, d_wt + O_W4D, bufA, smW, aP, aD, o_base, col_base, tid);
    unpack_acc(aP, fP); unpack_acc(aD, fD);
#pragma unroll
    for (int oo = 0; oo < 8; oo++) {
        int o3 = (o_base + oo) * 3;
        fP[oo][0] += scf[si0][o3];     fP[oo][1] += scf[si0][o3 + 1]; fP[oo][2] += scf[si0][o3 + 2];
        fP[oo][3] += scf[si1][o3];     fP[oo][4] += scf[si1][o3 + 1]; fP[oo][5] += scf[si1][o3 + 2];
        fD[oo][0] += scd[si0][o3];     fD[oo][1] += scd[si0][o3 + 1]; fD[oo][2] += scd[si0][o3 + 2];
        fD[oo][3] += scd[si1][o3];     fD[oo][4] += scd[si1][o3 + 1]; fD[oo][5] += scd[si1][o3 + 2];
    }
    vn_combine(fP, fD);
    store_tile<72>(bufA, fP, o_base, col_base);   // fills all 256 rows collectively

    // L5: vn5
    zero_acc(aP);
    mm_one2<256, 256, 72, 32, 384>(d_wt + O_W5, bufA, smW, aP, o_base, col_base, tid);
    unpack_acc(aP, fP);
    store_tile<72>(bufA, fP, o_base, col_base);

    // write h5 scratch
#pragma unroll
    for (int oo = 0; oo < 8; oo++) {
        float* g = d_h5s + (size_t)(o_base + oo) * NT3;
        if (v0) { g[(size_t)nA0*3] = fP[oo][0]; g[(size_t)nA0*3+1] = fP[oo][1]; g[(size_t)nA0*3+2] = fP[oo][2]; }
        if (v1) { g[(size_t)nA1*3] = fP[oo][3]; g[(size_t)nA1*3+1] = fP[oo][4]; g[(size_t)nA1*3+2] = fP[oo][5]; }
    }

    // L5d: d = Wd2 @ Y
    zero_acc(aD);
    mm_one2<256, 256, 72, 32, 384>(d_wt + O_WD2, bufA, smW, aD, o_base, col_base, tid);
    unpack_acc(aD, fD);

#pragma unroll
    for (int oo = 0; oo < 8; oo++) {
        if (v0) {
            float dot0 = fP[oo][0]*fD[oo][0] + fP[oo][1]*fD[oo][1] + fP[oo][2]*fD[oo][2];
            atomicMax(&sk[si0 * 256 + o_base + oo], packkey(dot0, (unsigned)nA0));
        }
        if (v1) {
            float dot1 = fP[oo][3]*fD[oo][3] + fP[oo][4]*fD[oo][4] + fP[oo][5]*fD[oo][5];
            atomicMax(&sk[si1 * 256 + o_base + oo], packkey(dot1, (unsigned)nA1));
        }
    }
    __syncthreads();
    for (int i = tid; i < 512; i += 384) {
        u64 v = sk[i];
        if (v) atomicMax(&d_key2[(seg0 + (i >> 8)) * 256 + (i & 255)], v);
    }
}

// ---------------------------------------------------------------------------
// gather + relu5 -> output
// ---------------------------------------------------------------------------
__global__ void k_relu5(float* __restrict__ out)
{
    __shared__ float G[256][3];
    int seg = blockIdx.x, c = threadIdx.x;
    u64 key = d_key2[seg * 256 + c];
    unsigned int idx = 0xFFFFFFFFu - (unsigned int)(key & 0xFFFFFFFFull);
    if (idx >= NPTS) idx = 0;
    float g0 = d_h5s[(size_t)c * NT3 + (size_t)idx * 3 + 0];
    float g1 = d_h5s[(size_t)c * NT3 + (size_t)idx * 3 + 1];
    float g2 = d_h5s[(size_t)c * NT3 + (size_t)idx * 3 + 2];
    G[c][0] = g0; G[c][1] = g1; G[c][2] = g2;
    __syncthreads();
    float a0 = 0.f, a1 = 0.f, a2 = 0.f;
    const float* w = d_wt + O_WR5;
    for (int k = 0; k < 256; k++) {
        float ww = w[k * 256 + c];
        a0 += ww * G[k][0]; a1 += ww * G[k][1]; a2 += ww * G[k][2];
    }
    float dot = g0 * a0 + g1 * a1 + g2 * a2;
    float dn  = a0 * a0 + a1 * a1 + a2 * a2;
    float o0 = g0, o1 = g1, o2 = g2;
    if (dot < 0.f) {
        float s = dot / (dn + EPSV);
        o0 -= s * a0; o1 -= s * a1; o2 -= s * a2;
    }
    out[seg * 768 + c * 3 + 0] = o0;
    out[seg * 768 + c * 3 + 1] = o1;
    out[seg * 768 + c * 3 + 2] = o2;
}

// ---------------------------------------------------------------------------
// host launcher
// ---------------------------------------------------------------------------
extern "C" void kernel_launch(void* const* d_in, const int* in_sizes, int n_in,
                              void* d_out, int out_size)
{
    const float* x      = (const float*)d_in[0];
    const int*   radius = (const int*)d_in[1];
    const float* W4f    = (const float*)d_in[9];
    const float* W4d    = (const float*)d_in[10];

    cudaFuncSetAttribute(k_stage1, cudaFuncAttributeMaxDynamicSharedMemorySize, 139264);
    cudaFuncSetAttribute(k_stage2, cudaFuncAttributeMaxDynamicSharedMemorySize, 204800);

    k_initkeys<<<32, 256>>>();

    dim3 tb(32, 8);
    TList t128;
    t128.src[0] = (const float*)d_in[2];  t128.off[0] = O_W1F;
    t128.src[1] = (const float*)d_in[3];  t128.off[1] = O_W1D;
    t128.src[2] = (const float*)d_in[4];  t128.off[2] = O_W2F;
    t128.src[3] = (const float*)d_in[5];  t128.off[3] = O_W2D;
    t128.src[4] = (const float*)d_in[6];  t128.off[4] = O_W3;
    t128.src[5] = (const float*)d_in[7];  t128.off[5] = O_WD1;
    t128.src[6] = (const float*)d_in[8];  t128.off[6] = O_WR3;
    k_tmany<<<dim3(4, 4, 7), tb>>>(t128, 128, 128);

    TList t256;
    t256.src[0] = (const float*)d_in[9];   t256.off[0] = O_W4F;
    t256.src[1] = (const float*)d_in[10];  t256.off[1] = O_W4D;
    t256.src[2] = (const float*)d_in[11];  t256.off[2] = O_W5;
    t256.src[3] = (const float*)d_in[12];  t256.off[3] = O_WD2;
    t256.src[4] = (const float*)d_in[13];  t256.off[4] = O_WR5;
    t256.src[5] = t256.src[4];             t256.off[5] = O_WR5;
    t256.src[6] = t256.src[4];             t256.off[6] = O_WR5;
    k_tmany<<<dim3(8, 8, 5), tb>>>(t256, 256, 256);

    k_stage1<<<(NPTS + 47) / 48, 384, 139264>>>(x, radius);
    k_relu3<<<NSEG, 128>>>();
    k_c4<<<NSEG, 256>>>(W4f, W4d);
    k_stage2<<<(NPTS + 23) / 24, 384, 204800>>>(x, radius);
    k_relu5<<<NSEG, 256>>>((float*)d_out);
}